// round 2
// baseline (speedup 1.0000x reference)
#include <cuda_runtime.h>
#include <cstdint>
#include <math.h>

#define Bz   4
#define Tz   1024
#define Cz   1024
#define Hz   16
#define Nz   64
#define BTz  (Bz*Tz)

// ---------------- scratch (device globals; no allocation allowed) ----------------
__device__ float g_xr[BTz*Cz];
__device__ float g_xw[BTz*Cz];
__device__ float g_xk[BTz*Cz];
__device__ float g_xv[BTz*Cz];
__device__ float g_xa[BTz*Cz];
__device__ float g_xg[BTz*Cz];
__device__ float g_r [BTz*Cz];
__device__ float g_k [BTz*Cz];
__device__ float g_v [BTz*Cz];
__device__ float g_wd[BTz*Cz];   // decay = exp(-exp(w))
__device__ float g_a [BTz*Cz];
__device__ float g_g [BTz*Cz];
__device__ float g_aa[BTz*Cz];   // -kk
__device__ float g_bb[BTz*Cz];   // kk*a
__device__ float g_h [BTz*128];  // LoRA hidden (max 128)
__device__ float g_o [BTz*Cz];   // scan output
__device__ float g_yg[BTz*Cz];   // (groupnorm(o)+bonus)*g

// ---------------- token shift + 6-way mix ----------------
__global__ void mix_kernel(const float* __restrict__ x,
                           const float* __restrict__ mr, const float* __restrict__ mw,
                           const float* __restrict__ mk, const float* __restrict__ mv,
                           const float* __restrict__ ma, const float* __restrict__ mg)
{
    int idx = blockIdx.x * blockDim.x + threadIdx.x;     // float4 index
    const int total = BTz * Cz / 4;
    if (idx >= total) return;
    int c4 = idx % (Cz / 4);
    int bt = idx / (Cz / 4);
    int t  = bt % Tz;
    const float4* x4 = (const float4*)x;
    float4 cur = x4[idx];
    float4 prev = make_float4(0.f, 0.f, 0.f, 0.f);
    if (t > 0) prev = x4[idx - Cz / 4];
    float4 xx = make_float4(prev.x - cur.x, prev.y - cur.y, prev.z - cur.z, prev.w - cur.w);
    int c = c4 * 4;
#define DO_MIX(dst, m) {                                                     \
        float4 mm = *(const float4*)((m) + c);                               \
        float4 o;                                                            \
        o.x = cur.x + xx.x * mm.x;  o.y = cur.y + xx.y * mm.y;               \
        o.z = cur.z + xx.z * mm.z;  o.w = cur.w + xx.w * mm.w;               \
        ((float4*)(dst))[idx] = o; }
    DO_MIX(g_xr, mr); DO_MIX(g_xw, mw); DO_MIX(g_xk, mk);
    DO_MIX(g_xv, mv); DO_MIX(g_xa, ma); DO_MIX(g_xg, mg);
#undef DO_MIX
}

// ---------------- generic tiled SGEMM with fused epilogue ----------------
// EPI: 0=identity, 1=tanh, 2=sigmoid(acc+bias), 3=decay: exp(-exp(-softplus(-(acc+bias))-0.5))
template<int EPI>
__device__ __forceinline__ float apply_epi(float acc, float b)
{
    float pre = acc + b;
    if (EPI == 0) return pre;
    if (EPI == 1) return tanhf(pre);
    if (EPI == 2) return 1.f / (1.f + expf(-pre));
    // EPI == 3
    float sp = (pre > -30.f) ? log1pf(expf(-pre)) : -pre;   // softplus(-pre)
    float w  = -sp - 0.5f;
    return expf(-expf(w));
}

template<int BM, int BN, int BK, int TM, int TN, int EPI>
__global__ __launch_bounds__((BM/TM)*(BN/TN))
void sgemm_kernel(int M, int N, int K,
                  const float* __restrict__ A, const float* __restrict__ B,
                  float* __restrict__ C, const float* __restrict__ bias)
{
    constexpr int THREADS = (BM/TM)*(BN/TN);
    __shared__ __align__(16) float As[BK][BM];
    __shared__ __align__(16) float Bs[BK][BN];
    const int tid = threadIdx.x;
    const int tx  = tid % (BN/TN);
    const int ty  = tid / (BN/TN);
    const int row0 = blockIdx.y * BM;
    const int col0 = blockIdx.x * BN;
    float acc[TM][TN];
#pragma unroll
    for (int i = 0; i < TM; i++)
#pragma unroll
        for (int j = 0; j < TN; j++) acc[i][j] = 0.f;

    constexpr int A_VECS = BM*BK/4/THREADS;
    constexpr int B_VECS = BK*BN/4/THREADS;

    for (int k0 = 0; k0 < K; k0 += BK) {
#pragma unroll
        for (int v = 0; v < A_VECS; v++) {
            int idx = (tid + v*THREADS) * 4;          // tile layout r*BK + c
            int r = idx / BK, c = idx % BK;
            float4 f = *(const float4*)(A + (size_t)(row0 + r) * K + k0 + c);
            As[c+0][r] = f.x; As[c+1][r] = f.y; As[c+2][r] = f.z; As[c+3][r] = f.w;
        }
#pragma unroll
        for (int v = 0; v < B_VECS; v++) {
            int idx = (tid + v*THREADS) * 4;          // tile layout r*BN + c
            int r = idx / BN, c = idx % BN;
            *(float4*)&Bs[r][c] = *(const float4*)(B + (size_t)(k0 + r) * N + col0 + c);
        }
        __syncthreads();
#pragma unroll
        for (int kk = 0; kk < BK; kk++) {
            float ra[TM], rb[TN];
#pragma unroll
            for (int i = 0; i < TM; i++) ra[i] = As[kk][ty*TM + i];
#pragma unroll
            for (int j = 0; j < TN; j++) rb[j] = Bs[kk][tx*TN + j];
#pragma unroll
            for (int i = 0; i < TM; i++)
#pragma unroll
                for (int j = 0; j < TN; j++) acc[i][j] = fmaf(ra[i], rb[j], acc[i][j]);
        }
        __syncthreads();
    }
#pragma unroll
    for (int i = 0; i < TM; i++) {
        int r = row0 + ty*TM + i;
#pragma unroll
        for (int j = 0; j < TN; j++) {
            int c = col0 + tx*TN + j;
            float b = bias ? bias[c] : 0.f;
            C[(size_t)r * N + c] = apply_epi<EPI>(acc[i][j], b);
        }
    }
}

// ---------------- kk normalize, aa, bb, k update ----------------
__global__ void prep_kernel(const float* __restrict__ kkw, const float* __restrict__ kaw)
{
    int gw   = (blockIdx.x * blockDim.x + threadIdx.x) >> 5;
    int lane = threadIdx.x & 31;
    if (gw >= BTz * Hz) return;
    int bt = gw / Hz, h = gw % Hz;
    int c0 = h * 64 + lane, c1 = c0 + 32;
    size_t base = (size_t)bt * Cz;
    float k0 = g_k[base + c0], k1 = g_k[base + c1];
    float kk0 = k0 * kkw[c0], kk1 = k1 * kkw[c1];
    float ss = kk0*kk0 + kk1*kk1;
#pragma unroll
    for (int m = 16; m > 0; m >>= 1) ss += __shfl_xor_sync(0xffffffffu, ss, m);
    float inv = 1.f / fmaxf(sqrtf(ss), 1e-12f);
    float a0 = g_a[base + c0], a1v = g_a[base + c1];
    kk0 *= inv; kk1 *= inv;
    g_aa[base + c0] = -kk0;       g_aa[base + c1] = -kk1;
    g_bb[base + c0] = kk0 * a0;   g_bb[base + c1] = kk1 * a1v;
    g_k [base + c0] = k0 * (1.f + (a0  - 1.f) * kaw[c0]);
    g_k [base + c1] = k1 * (1.f + (a1v - 1.f) * kaw[c1]);
}

// ---------------- sequential RWKV7 state scan ----------------
// One block per (b,h). 128 threads: tid = i*2 + jq; thread owns S[i][jq*32 .. jq*32+31].
__global__ __launch_bounds__(128)
void scan_kernel(const float* __restrict__ r, const float* __restrict__ wdec,
                 const float* __restrict__ k, const float* __restrict__ aa,
                 const float* __restrict__ bb, const float* __restrict__ v,
                 float* __restrict__ o)
{
    const int bh = blockIdx.x;
    const int b = bh / Hz, h = bh % Hz;
    const int tid = threadIdx.x;
    const int i  = tid >> 1;
    const int jq = tid & 1;
    const int jb = jq * 32;

    __shared__ __align__(16) float sm[2][6*64];   // vec layout: r,w,k,aa,bb,v @ 64 apart
    float S[32];
#pragma unroll
    for (int q = 0; q < 32; q++) S[q] = 0.f;

    const size_t base = (size_t)b * Tz * Cz + h * 64;
    const float* vp[6] = { r + base, wdec + base, k + base, aa + base, bb + base, v + base };

    // each thread resolves its 3 fixed (vector, offset) load slots once
    const float* myp[3]; int mys[3];
#pragma unroll
    for (int u = 0; u < 3; u++) {
        int lin = u * 128 + tid;
        int vec = lin >> 6;
        int idx = lin & 63;
        const float* p = vp[0];
        if (vec == 1) p = vp[1]; else if (vec == 2) p = vp[2];
        else if (vec == 3) p = vp[3]; else if (vec == 4) p = vp[4];
        else if (vec == 5) p = vp[5];
        myp[u] = p + idx;
        mys[u] = lin;
    }

    // preload t=0 into buffer 0
#pragma unroll
    for (int u = 0; u < 3; u++) sm[0][mys[u]] = myp[u][0];
    __syncthreads();

    float* obase = o + base;
    for (int t = 0; t < Tz; t++) {
        const int cur = t & 1;
        if (t + 1 < Tz) {
            size_t off = (size_t)(t + 1) * Cz;
#pragma unroll
            for (int u = 0; u < 3; u++) sm[cur ^ 1][mys[u]] = myp[u][off];
        }
        const float* s_r  = &sm[cur][0];
        const float* s_w  = &sm[cur][64];
        const float* s_k  = &sm[cur][128];
        const float* s_aa = &sm[cur][192];
        const float* s_bb = &sm[cur][256];
        const float* s_v  = &sm[cur][320];

        float sa = 0.f;
#pragma unroll
        for (int q = 0; q < 32; q++) sa = fmaf(S[q], s_aa[jb + q], sa);
        sa += __shfl_xor_sync(0xffffffffu, sa, 1);

        const float vi = s_v[i];
        float out = 0.f;
#pragma unroll
        for (int q = 0; q < 32; q++) {
            float Sj = fmaf(S[q], s_w[jb + q], fmaf(sa, s_bb[jb + q], vi * s_k[jb + q]));
            S[q] = Sj;
            out = fmaf(Sj, s_r[jb + q], out);
        }
        out += __shfl_xor_sync(0xffffffffu, out, 1);
        if (jq == 0) obase[(size_t)t * Cz + i] = out;
        __syncthreads();
    }
}

// ---------------- groupnorm + rk bonus + gate ----------------
__global__ void post_kernel(const float* __restrict__ rk,
                            const float* __restrict__ gamma, const float* __restrict__ beta)
{
    int gw   = (blockIdx.x * blockDim.x + threadIdx.x) >> 5;
    int lane = threadIdx.x & 31;
    if (gw >= BTz * Hz) return;
    int bt = gw / Hz, h = gw % Hz;
    int c0 = h * 64 + lane, c1 = c0 + 32;
    size_t base = (size_t)bt * Cz;
    float o0 = g_o[base + c0], o1 = g_o[base + c1];
    float s1 = o0 + o1;
    float s2 = o0*o0 + o1*o1;
    float r0 = g_r[base + c0], r1 = g_r[base + c1];
    float k0 = g_k[base + c0], k1 = g_k[base + c1];
    float bon = r0 * k0 * rk[h * 64 + lane] + r1 * k1 * rk[h * 64 + lane + 32];
#pragma unroll
    for (int m = 16; m > 0; m >>= 1) {
        s1  += __shfl_xor_sync(0xffffffffu, s1,  m);
        s2  += __shfl_xor_sync(0xffffffffu, s2,  m);
        bon += __shfl_xor_sync(0xffffffffu, bon, m);
    }
    float mu   = s1 * (1.f / 64.f);
    float var  = s2 * (1.f / 64.f) - mu * mu;
    float rstd = rsqrtf(var + 0.00064f);
    float v0 = g_v[base + c0], v1 = g_v[base + c1];
    float y0 = (o0 - mu) * rstd * gamma[c0] + beta[c0] + bon * v0;
    float y1 = (o1 - mu) * rstd * gamma[c1] + beta[c1] + bon * v1;
    g_yg[base + c0] = y0 * g_g[base + c0];
    g_yg[base + c1] = y1 * g_g[base + c1];
}

// ---------------- launch ----------------
extern "C" void kernel_launch(void* const* d_in, const int* in_sizes, int n_in,
                              void* d_out, int out_size)
{
    const float* x    = (const float*)d_in[0];
    const float* x_r  = (const float*)d_in[1];
    const float* x_w  = (const float*)d_in[2];
    const float* x_k  = (const float*)d_in[3];
    const float* x_v  = (const float*)d_in[4];
    const float* x_a  = (const float*)d_in[5];
    const float* x_g  = (const float*)d_in[6];
    const float* w0   = (const float*)d_in[7];
    const float* w1   = (const float*)d_in[8];
    const float* w2   = (const float*)d_in[9];
    const float* a0   = (const float*)d_in[10];
    const float* a1   = (const float*)d_in[11];
    const float* a2   = (const float*)d_in[12];
    // d_in[13..15] = v0,v1,v2 (unused: first layer, v_first = v)
    const float* g1   = (const float*)d_in[16];
    const float* g2   = (const float*)d_in[17];
    const float* k_k  = (const float*)d_in[18];
    const float* k_a  = (const float*)d_in[19];
    const float* r_k  = (const float*)d_in[20];
    const float* Wr   = (const float*)d_in[21];
    const float* Wk   = (const float*)d_in[22];
    const float* Wv   = (const float*)d_in[23];
    const float* Wo   = (const float*)d_in[24];
    const float* lg   = (const float*)d_in[25];
    const float* lb   = (const float*)d_in[26];

    void *p_xr, *p_xw, *p_xk, *p_xv, *p_xa, *p_xg;
    void *p_r, *p_k, *p_v, *p_wd, *p_a, *p_g, *p_aa, *p_bb, *p_h, *p_o, *p_yg;
    cudaGetSymbolAddress(&p_xr, g_xr); cudaGetSymbolAddress(&p_xw, g_xw);
    cudaGetSymbolAddress(&p_xk, g_xk); cudaGetSymbolAddress(&p_xv, g_xv);
    cudaGetSymbolAddress(&p_xa, g_xa); cudaGetSymbolAddress(&p_xg, g_xg);
    cudaGetSymbolAddress(&p_r,  g_r);  cudaGetSymbolAddress(&p_k,  g_k);
    cudaGetSymbolAddress(&p_v,  g_v);  cudaGetSymbolAddress(&p_wd, g_wd);
    cudaGetSymbolAddress(&p_a,  g_a);  cudaGetSymbolAddress(&p_g,  g_g);
    cudaGetSymbolAddress(&p_aa, g_aa); cudaGetSymbolAddress(&p_bb, g_bb);
    cudaGetSymbolAddress(&p_h,  g_h);  cudaGetSymbolAddress(&p_o,  g_o);
    cudaGetSymbolAddress(&p_yg, g_yg);

    float* xr = (float*)p_xr; float* xw = (float*)p_xw; float* xk = (float*)p_xk;
    float* xv = (float*)p_xv; float* xa = (float*)p_xa; float* xg = (float*)p_xg;
    float* rb = (float*)p_r;  float* kb = (float*)p_k;  float* vb = (float*)p_v;
    float* wd = (float*)p_wd; float* ab = (float*)p_a;  float* gb = (float*)p_g;
    float* aab = (float*)p_aa; float* bbb = (float*)p_bb; float* hb = (float*)p_h;
    float* ob = (float*)p_o;  float* yg = (float*)p_yg;

    // 1. token shift + mix
    mix_kernel<<<(BTz*Cz/4 + 255)/256, 256>>>(x, x_r, x_w, x_k, x_v, x_a, x_g);

    // 2. big projections
    dim3 bg(Cz/128, BTz/128);
    sgemm_kernel<128,128,16,8,8,0><<<bg, 256>>>(BTz, Cz, Cz, xr, Wr, rb, nullptr);
    sgemm_kernel<128,128,16,8,8,0><<<bg, 256>>>(BTz, Cz, Cz, xk, Wk, kb, nullptr);
    sgemm_kernel<128,128,16,8,8,0><<<bg, 256>>>(BTz, Cz, Cz, xv, Wv, vb, nullptr);

    // 3. decay LoRA: h = tanh(xw@w1); decay = exp(-exp(-softplus(-(w0+h@w2))-0.5))
    sgemm_kernel<64,64,16,4,4,1><<<dim3(1, BTz/64), 256>>>(BTz, 64, Cz, xw, w1, hb, nullptr);
    sgemm_kernel<128,128,16,8,8,3><<<bg, 256>>>(BTz, Cz, 64, hb, w2, wd, w0);

    // 4. a LoRA: a = sigmoid(a0 + (xa@a1)@a2)
    sgemm_kernel<64,64,16,4,4,0><<<dim3(1, BTz/64), 256>>>(BTz, 64, Cz, xa, a1, hb, nullptr);
    sgemm_kernel<128,128,16,8,8,2><<<bg, 256>>>(BTz, Cz, 64, hb, a2, ab, a0);

    // 5. g LoRA: g = sigmoid(xg@g1)@g2
    sgemm_kernel<64,64,16,4,4,2><<<dim3(2, BTz/64), 256>>>(BTz, 128, Cz, xg, g1, hb, nullptr);
    sgemm_kernel<128,128,16,8,8,0><<<bg, 256>>>(BTz, Cz, 128, hb, g2, gb, nullptr);

    // 6. kk normalize / aa / bb / k update
    prep_kernel<<<BTz*Hz/8, 256>>>(k_k, k_a);

    // 7. sequential scan
    scan_kernel<<<Bz*Hz, 128>>>(rb, wd, kb, aab, bbb, vb, ob);

    // 8. groupnorm + bonus + gate
    post_kernel<<<BTz*Hz/8, 256>>>(r_k, lg, lb);

    // 9. output projection
    sgemm_kernel<128,128,16,8,8,0><<<bg, 256>>>(BTz, Cz, Cz, yg, Wo, (float*)d_out, nullptr);

    // 10. v_first (second tuple element) if the harness expects it
    if (out_size >= 2 * BTz * Cz) {
        cudaMemcpyAsync((float*)d_out + (size_t)BTz * Cz, vb,
                        sizeof(float) * (size_t)BTz * Cz, cudaMemcpyDeviceToDevice);
    }
}

// round 3
// speedup vs baseline: 1.2494x; 1.2494x over previous
#include <cuda_runtime.h>
#include <cuda_bf16.h>
#include <cstdint>
#include <math.h>

#define Bz   4
#define Tz   1024
#define Cz   1024
#define Hz   16
#define BTz  (Bz*Tz)

typedef __nv_bfloat16  bf16;
typedef __nv_bfloat162 bf162;

// ---------------- scratch (device globals; no allocation allowed) ----------------
__device__ float g_r [BTz*Cz], g_k [BTz*Cz], g_v [BTz*Cz], g_wd[BTz*Cz];
__device__ float g_a [BTz*Cz], g_g [BTz*Cz], g_aa[BTz*Cz], g_bb[BTz*Cz], g_o [BTz*Cz];

__device__ bf16 g_xh[6*BTz*Cz], g_xl[6*BTz*Cz];      // mixed streams hi/lo (r,w,k,v,a,g)
__device__ bf16 g_ygh[BTz*Cz],  g_ygl[BTz*Cz];       // (gn(o)+bonus)*g hi/lo
__device__ bf16 g_hh[BTz*128],  g_hl[BTz*128];       // LoRA hidden hi/lo

#define O_Wr 0
#define O_Wk (Cz*Cz)
#define O_Wv (2*Cz*Cz)
#define O_Wo (3*Cz*Cz)
#define O_w1 (4*Cz*Cz)
#define O_w2 (O_w1 + Cz*64)
#define O_a1 (O_w2 + 64*Cz)
#define O_a2 (O_a1 + Cz*64)
#define O_g1 (O_a2 + 64*Cz)
#define O_g2 (O_g1 + Cz*128)
#define WPOOL (O_g2 + 128*Cz)
__device__ bf16 g_wh[WPOOL], g_wl[WPOOL];

// ---------------- small helpers ----------------
__device__ __forceinline__ uint32_t su32(const void* p) {
    return (uint32_t)__cvta_generic_to_shared(p);
}
__device__ __forceinline__ void ldsm4(uint32_t& a0, uint32_t& a1, uint32_t& a2, uint32_t& a3, uint32_t addr) {
    asm volatile("ldmatrix.sync.aligned.m8n8.x4.shared.b16 {%0,%1,%2,%3},[%4];"
                 : "=r"(a0), "=r"(a1), "=r"(a2), "=r"(a3) : "r"(addr));
}
__device__ __forceinline__ void ldsm4t(uint32_t& a0, uint32_t& a1, uint32_t& a2, uint32_t& a3, uint32_t addr) {
    asm volatile("ldmatrix.sync.aligned.m8n8.x4.trans.shared.b16 {%0,%1,%2,%3},[%4];"
                 : "=r"(a0), "=r"(a1), "=r"(a2), "=r"(a3) : "r"(addr));
}
__device__ __forceinline__ void mma16816(float* c, const uint32_t* a, const uint32_t* b) {
    asm volatile("mma.sync.aligned.m16n8k16.row.col.f32.bf16.bf16.f32 "
                 "{%0,%1,%2,%3},{%4,%5,%6,%7},{%8,%9},{%0,%1,%2,%3};"
                 : "+f"(c[0]), "+f"(c[1]), "+f"(c[2]), "+f"(c[3])
                 : "r"(a[0]), "r"(a[1]), "r"(a[2]), "r"(a[3]), "r"(b[0]), "r"(b[1]));
}
__device__ __forceinline__ void pack_hl(float4 o, uint2& h, uint2& l) {
    bf162 h0 = __floats2bfloat162_rn(o.x, o.y);
    bf162 h1 = __floats2bfloat162_rn(o.z, o.w);
    h.x = *(uint32_t*)&h0;  h.y = *(uint32_t*)&h1;
    bf162 l0 = __floats2bfloat162_rn(o.x - __bfloat162float(h0.x), o.y - __bfloat162float(h0.y));
    bf162 l1 = __floats2bfloat162_rn(o.z - __bfloat162float(h1.x), o.w - __bfloat162float(h1.y));
    l.x = *(uint32_t*)&l0;  l.y = *(uint32_t*)&l1;
}

// ---------------- weight split fp32 -> bf16 hi/lo ----------------
__global__ void split_kernel(const float* __restrict__ src, bf16* __restrict__ hi,
                             bf16* __restrict__ lo, int n4)
{
    int i = blockIdx.x * blockDim.x + threadIdx.x;
    if (i >= n4) return;
    float4 v = ((const float4*)src)[i];
    uint2 h, l;
    pack_hl(v, h, l);
    ((uint2*)hi)[i] = h;
    ((uint2*)lo)[i] = l;
}

// ---------------- token shift + 6-way mix, emitting hi/lo bf16 ----------------
__global__ void mix_kernel(const float* __restrict__ x,
                           const float* __restrict__ mr, const float* __restrict__ mw,
                           const float* __restrict__ mk, const float* __restrict__ mv,
                           const float* __restrict__ ma, const float* __restrict__ mg,
                           bf16* __restrict__ xh, bf16* __restrict__ xl)
{
    int idx = blockIdx.x * blockDim.x + threadIdx.x;     // float4 index
    const int total = BTz * Cz / 4;
    if (idx >= total) return;
    int c4 = idx % (Cz / 4);
    int bt = idx / (Cz / 4);
    int t  = bt % Tz;
    const float4* x4 = (const float4*)x;
    float4 cur = x4[idx];
    float4 prev = make_float4(0.f, 0.f, 0.f, 0.f);
    if (t > 0) prev = x4[idx - Cz / 4];
    float4 xx = make_float4(prev.x - cur.x, prev.y - cur.y, prev.z - cur.z, prev.w - cur.w);
    int c = c4 * 4;
    const float* ms[6] = { mr, mw, mk, mv, ma, mg };
#pragma unroll
    for (int s = 0; s < 6; s++) {
        float4 mm = *(const float4*)(ms[s] + c);
        float4 o;
        o.x = cur.x + xx.x * mm.x;  o.y = cur.y + xx.y * mm.y;
        o.z = cur.z + xx.z * mm.z;  o.w = cur.w + xx.w * mm.w;
        uint2 h, l;
        pack_hl(o, h, l);
        ((uint2*)(xh + (size_t)s * BTz * Cz))[idx] = h;
        ((uint2*)(xl + (size_t)s * BTz * Cz))[idx] = l;
    }
}

// ---------------- epilogues ----------------
// EPI: 0=identity, 1=tanh, 2=sigmoid(acc+bias), 3=decay chain
template<int EPI>
__device__ __forceinline__ float apply_epi(float acc, float b)
{
    float pre = acc + b;
    if (EPI == 0) return pre;
    if (EPI == 1) return tanhf(pre);
    if (EPI == 2) return 1.f / (1.f + expf(-pre));
    float sp = (pre > -30.f) ? log1pf(expf(-pre)) : -pre;   // softplus(-pre)
    return expf(-expf(-sp - 0.5f));
}

// ---------------- bf16x3 tensor-core GEMM: C = Ah*Bh + Ah*Bl + Al*Bh ----------------
// A row-major [M,K], B row-major [K,N]. OUT: 0 -> fp32 C, 1 -> hi/lo bf16 Ch/Cl.
template<int BM, int BN, int BK, int WM, int WN, int EPI, int OUT>
__global__ __launch_bounds__((BM/WM)*(BN/WN)*32)
void mma_gemm(int M, int N, int K,
              const bf16* __restrict__ Ah, const bf16* __restrict__ Al,
              const bf16* __restrict__ Bh, const bf16* __restrict__ Bl,
              float* __restrict__ C, bf16* __restrict__ Ch, bf16* __restrict__ Cl,
              const float* __restrict__ bias)
{
    constexpr int WARPS  = (BM/WM)*(BN/WN);
    constexpr int THREADS = WARPS * 32;
    constexpr int MFR = WM / 16, NFR = WN / 8;
    constexpr int AKp = BK + 8;    // padded strides (halves) -> conflict-free ldmatrix
    constexpr int BNp = BN + 8;
    __shared__ __align__(16) bf16 sA[2 * BM * AKp];
    __shared__ __align__(16) bf16 sB[2 * BK * BNp];
    const int tid = threadIdx.x, lane = tid & 31, warp = tid >> 5;
    const int wN = warp % (BN/WN), wM = warp / (BN/WN);
    const int row0 = blockIdx.y * BM, col0 = blockIdx.x * BN;

    float acc[MFR][NFR][4];
#pragma unroll
    for (int i = 0; i < MFR; i++)
#pragma unroll
        for (int j = 0; j < NFR; j++)
#pragma unroll
            for (int q = 0; q < 4; q++) acc[i][j][q] = 0.f;

    uint32_t aBase[MFR], bBase[NFR/2];
#pragma unroll
    for (int fm = 0; fm < MFR; fm++)
        aBase[fm] = su32(&sA[(wM*WM + fm*16 + (lane & 15)) * AKp + ((lane >> 4) * 8)]);
#pragma unroll
    for (int p = 0; p < NFR/2; p++)
        bBase[p] = su32(&sB[(lane & 15) * BNp + wN*WN + p*16 + ((lane >> 4) * 8)]);

    constexpr uint32_t A_LO = BM * AKp * 2;   // byte offset hi -> lo plane
    constexpr uint32_t B_LO = BK * BNp * 2;

    for (int k0 = 0; k0 < K; k0 += BK) {
        for (int i = tid; i < BM * (BK/8); i += THREADS) {
            int r = i / (BK/8), c = (i % (BK/8)) * 8;
            size_t g = (size_t)(row0 + r) * K + k0 + c;
            *(uint4*)&sA[r*AKp + c]            = *(const uint4*)(Ah + g);
            *(uint4*)&sA[BM*AKp + r*AKp + c]   = *(const uint4*)(Al + g);
        }
        for (int i = tid; i < BK * (BN/8); i += THREADS) {
            int r = i / (BN/8), c = (i % (BN/8)) * 8;
            size_t g = (size_t)(k0 + r) * N + col0 + c;
            *(uint4*)&sB[r*BNp + c]            = *(const uint4*)(Bh + g);
            *(uint4*)&sB[BK*BNp + r*BNp + c]   = *(const uint4*)(Bl + g);
        }
        __syncthreads();
#pragma unroll
        for (int kk = 0; kk < BK; kk += 16) {
            uint32_t Afh[MFR][4], Afl[MFR][4], Bfh[NFR][2], Bfl[NFR][2];
#pragma unroll
            for (int fm = 0; fm < MFR; fm++) {
                ldsm4(Afh[fm][0], Afh[fm][1], Afh[fm][2], Afh[fm][3], aBase[fm] + kk*2);
                ldsm4(Afl[fm][0], Afl[fm][1], Afl[fm][2], Afl[fm][3], aBase[fm] + A_LO + kk*2);
            }
#pragma unroll
            for (int p = 0; p < NFR/2; p++) {
                uint32_t t0, t1, t2, t3;
                ldsm4t(t0, t1, t2, t3, bBase[p] + kk*BNp*2);
                Bfh[2*p][0] = t0; Bfh[2*p][1] = t1; Bfh[2*p+1][0] = t2; Bfh[2*p+1][1] = t3;
                ldsm4t(t0, t1, t2, t3, bBase[p] + B_LO + kk*BNp*2);
                Bfl[2*p][0] = t0; Bfl[2*p][1] = t1; Bfl[2*p+1][0] = t2; Bfl[2*p+1][1] = t3;
            }
#pragma unroll
            for (int fm = 0; fm < MFR; fm++)
#pragma unroll
                for (int fn = 0; fn < NFR; fn++) {
                    mma16816(acc[fm][fn], Afh[fm], Bfh[fn]);
                    mma16816(acc[fm][fn], Afh[fm], Bfl[fn]);
                    mma16816(acc[fm][fn], Afl[fm], Bfh[fn]);
                }
        }
        __syncthreads();
    }

#pragma unroll
    for (int fm = 0; fm < MFR; fm++) {
        int r = row0 + wM*WM + fm*16 + (lane >> 2);
#pragma unroll
        for (int fn = 0; fn < NFR; fn++) {
            int c = col0 + wN*WN + fn*8 + 2*(lane & 3);
            float b0 = bias ? bias[c] : 0.f;
            float b1 = bias ? bias[c+1] : 0.f;
            float x0 = apply_epi<EPI>(acc[fm][fn][0], b0);
            float x1 = apply_epi<EPI>(acc[fm][fn][1], b1);
            float x2 = apply_epi<EPI>(acc[fm][fn][2], b0);
            float x3 = apply_epi<EPI>(acc[fm][fn][3], b1);
            if (OUT == 0) {
                *(float2*)&C[(size_t)r*N + c]     = make_float2(x0, x1);
                *(float2*)&C[(size_t)(r+8)*N + c] = make_float2(x2, x3);
            } else {
                bf162 h0 = __floats2bfloat162_rn(x0, x1);
                bf162 h1 = __floats2bfloat162_rn(x2, x3);
                *(bf162*)&Ch[(size_t)r*N + c]     = h0;
                *(bf162*)&Ch[(size_t)(r+8)*N + c] = h1;
                bf162 l0 = __floats2bfloat162_rn(x0 - __bfloat162float(h0.x), x1 - __bfloat162float(h0.y));
                bf162 l1 = __floats2bfloat162_rn(x2 - __bfloat162float(h1.x), x3 - __bfloat162float(h1.y));
                *(bf162*)&Cl[(size_t)r*N + c]     = l0;
                *(bf162*)&Cl[(size_t)(r+8)*N + c] = l1;
            }
        }
    }
}

// ---------------- kk normalize, aa, bb, k update ----------------
__global__ void prep_kernel(const float* __restrict__ kkw, const float* __restrict__ kaw)
{
    int gw   = (blockIdx.x * blockDim.x + threadIdx.x) >> 5;
    int lane = threadIdx.x & 31;
    if (gw >= BTz * Hz) return;
    int bt = gw / Hz, h = gw % Hz;
    int c0 = h * 64 + lane, c1 = c0 + 32;
    size_t base = (size_t)bt * Cz;
    float k0 = g_k[base + c0], k1 = g_k[base + c1];
    float kk0 = k0 * kkw[c0], kk1 = k1 * kkw[c1];
    float ss = kk0*kk0 + kk1*kk1;
#pragma unroll
    for (int m = 16; m > 0; m >>= 1) ss += __shfl_xor_sync(0xffffffffu, ss, m);
    float inv = 1.f / fmaxf(sqrtf(ss), 1e-12f);
    float a0 = g_a[base + c0], a1v = g_a[base + c1];
    kk0 *= inv; kk1 *= inv;
    g_aa[base + c0] = -kk0;       g_aa[base + c1] = -kk1;
    g_bb[base + c0] = kk0 * a0;   g_bb[base + c1] = kk1 * a1v;
    g_k [base + c0] = k0 * (1.f + (a0  - 1.f) * kaw[c0]);
    g_k [base + c1] = k1 * (1.f + (a1v - 1.f) * kaw[c1]);
}

// ---------------- sequential RWKV7 state scan ----------------
__global__ __launch_bounds__(128)
void scan_kernel(const float* __restrict__ r, const float* __restrict__ wdec,
                 const float* __restrict__ k, const float* __restrict__ aa,
                 const float* __restrict__ bb, const float* __restrict__ v,
                 float* __restrict__ o)
{
    const int bh = blockIdx.x;
    const int b = bh / Hz, h = bh % Hz;
    const int tid = threadIdx.x;
    const int i  = tid >> 1;
    const int jq = tid & 1;
    const int jb = jq * 32;

    __shared__ __align__(16) float sm[2][6*64];
    float S[32];
#pragma unroll
    for (int q = 0; q < 32; q++) S[q] = 0.f;

    const size_t base = (size_t)b * Tz * Cz + h * 64;
    const float* vp[6] = { r + base, wdec + base, k + base, aa + base, bb + base, v + base };

    const float* myp[3]; int mys[3];
#pragma unroll
    for (int u = 0; u < 3; u++) {
        int lin = u * 128 + tid;
        int vec = lin >> 6;
        int idx = lin & 63;
        const float* p = vp[0];
        if (vec == 1) p = vp[1]; else if (vec == 2) p = vp[2];
        else if (vec == 3) p = vp[3]; else if (vec == 4) p = vp[4];
        else if (vec == 5) p = vp[5];
        myp[u] = p + idx;
        mys[u] = lin;
    }

#pragma unroll
    for (int u = 0; u < 3; u++) sm[0][mys[u]] = myp[u][0];
    __syncthreads();

    float* obase = o + base;
    for (int t = 0; t < Tz; t++) {
        const int cur = t & 1;
        if (t + 1 < Tz) {
            size_t off = (size_t)(t + 1) * Cz;
#pragma unroll
            for (int u = 0; u < 3; u++) sm[cur ^ 1][mys[u]] = myp[u][off];
        }
        const float* s_r  = &sm[cur][0];
        const float* s_w  = &sm[cur][64];
        const float* s_k  = &sm[cur][128];
        const float* s_aa = &sm[cur][192];
        const float* s_bb = &sm[cur][256];
        const float* s_v  = &sm[cur][320];

        float sa = 0.f;
#pragma unroll
        for (int q = 0; q < 32; q++) sa = fmaf(S[q], s_aa[jb + q], sa);
        sa += __shfl_xor_sync(0xffffffffu, sa, 1);

        const float vi = s_v[i];
        float out = 0.f;
#pragma unroll
        for (int q = 0; q < 32; q++) {
            float Sj = fmaf(S[q], s_w[jb + q], fmaf(sa, s_bb[jb + q], vi * s_k[jb + q]));
            S[q] = Sj;
            out = fmaf(Sj, s_r[jb + q], out);
        }
        out += __shfl_xor_sync(0xffffffffu, out, 1);
        if (jq == 0) obase[(size_t)t * Cz + i] = out;
        __syncthreads();
    }
}

// ---------------- groupnorm + rk bonus + gate -> hi/lo bf16 ----------------
__global__ void post_kernel(const float* __restrict__ rk,
                            const float* __restrict__ gamma, const float* __restrict__ beta)
{
    int gw   = (blockIdx.x * blockDim.x + threadIdx.x) >> 5;
    int lane = threadIdx.x & 31;
    if (gw >= BTz * Hz) return;
    int bt = gw / Hz, h = gw % Hz;
    int c0 = h * 64 + lane, c1 = c0 + 32;
    size_t base = (size_t)bt * Cz;
    float o0 = g_o[base + c0], o1 = g_o[base + c1];
    float s1 = o0 + o1;
    float s2 = o0*o0 + o1*o1;
    float r0 = g_r[base + c0], r1 = g_r[base + c1];
    float k0 = g_k[base + c0], k1 = g_k[base + c1];
    float bon = r0 * k0 * rk[h * 64 + lane] + r1 * k1 * rk[h * 64 + lane + 32];
#pragma unroll
    for (int m = 16; m > 0; m >>= 1) {
        s1  += __shfl_xor_sync(0xffffffffu, s1,  m);
        s2  += __shfl_xor_sync(0xffffffffu, s2,  m);
        bon += __shfl_xor_sync(0xffffffffu, bon, m);
    }
    float mu   = s1 * (1.f / 64.f);
    float var  = s2 * (1.f / 64.f) - mu * mu;
    float rstd = rsqrtf(var + 0.00064f);
    float v0 = g_v[base + c0], v1 = g_v[base + c1];
    float y0 = ((o0 - mu) * rstd * gamma[c0] + beta[c0] + bon * v0) * g_g[base + c0];
    float y1 = ((o1 - mu) * rstd * gamma[c1] + beta[c1] + bon * v1) * g_g[base + c1];
    bf16 h0 = __float2bfloat16_rn(y0);
    bf16 h1 = __float2bfloat16_rn(y1);
    g_ygh[base + c0] = h0;  g_ygh[base + c1] = h1;
    g_ygl[base + c0] = __float2bfloat16_rn(y0 - __bfloat162float(h0));
    g_ygl[base + c1] = __float2bfloat16_rn(y1 - __bfloat162float(h1));
}

// ---------------- launch ----------------
extern "C" void kernel_launch(void* const* d_in, const int* in_sizes, int n_in,
                              void* d_out, int out_size)
{
    const float* x    = (const float*)d_in[0];
    const float* x_r  = (const float*)d_in[1];
    const float* x_w  = (const float*)d_in[2];
    const float* x_k  = (const float*)d_in[3];
    const float* x_v  = (const float*)d_in[4];
    const float* x_a  = (const float*)d_in[5];
    const float* x_g  = (const float*)d_in[6];
    const float* w0   = (const float*)d_in[7];
    const float* w1   = (const float*)d_in[8];
    const float* w2   = (const float*)d_in[9];
    const float* a0   = (const float*)d_in[10];
    const float* a1   = (const float*)d_in[11];
    const float* a2   = (const float*)d_in[12];
    const float* g1   = (const float*)d_in[16];
    const float* g2   = (const float*)d_in[17];
    const float* k_k  = (const float*)d_in[18];
    const float* k_a  = (const float*)d_in[19];
    const float* r_k  = (const float*)d_in[20];
    const float* Wr   = (const float*)d_in[21];
    const float* Wk   = (const float*)d_in[22];
    const float* Wv   = (const float*)d_in[23];
    const float* Wo   = (const float*)d_in[24];
    const float* lg   = (const float*)d_in[25];
    const float* lb   = (const float*)d_in[26];

    void *pr, *pk, *pv, *pwd, *pa, *pg, *paa, *pbb, *po;
    void *pxh, *pxl, *pygh, *pygl, *phh, *phl, *pwh, *pwl;
    cudaGetSymbolAddress(&pr,  g_r);   cudaGetSymbolAddress(&pk,  g_k);
    cudaGetSymbolAddress(&pv,  g_v);   cudaGetSymbolAddress(&pwd, g_wd);
    cudaGetSymbolAddress(&pa,  g_a);   cudaGetSymbolAddress(&pg,  g_g);
    cudaGetSymbolAddress(&paa, g_aa);  cudaGetSymbolAddress(&pbb, g_bb);
    cudaGetSymbolAddress(&po,  g_o);
    cudaGetSymbolAddress(&pxh, g_xh);  cudaGetSymbolAddress(&pxl, g_xl);
    cudaGetSymbolAddress(&pygh, g_ygh); cudaGetSymbolAddress(&pygl, g_ygl);
    cudaGetSymbolAddress(&phh, g_hh);  cudaGetSymbolAddress(&phl, g_hl);
    cudaGetSymbolAddress(&pwh, g_wh);  cudaGetSymbolAddress(&pwl, g_wl);

    float *rb = (float*)pr, *kb = (float*)pk, *vb = (float*)pv, *wd = (float*)pwd;
    float *ab = (float*)pa, *gb = (float*)pg, *aab = (float*)paa, *bbb = (float*)pbb;
    float *ob = (float*)po;
    bf16 *xh = (bf16*)pxh, *xl = (bf16*)pxl;
    bf16 *ygh = (bf16*)pygh, *ygl = (bf16*)pygl;
    bf16 *hh = (bf16*)phh, *hl = (bf16*)phl;
    bf16 *wh = (bf16*)pwh, *wl = (bf16*)pwl;

    const size_t S = (size_t)BTz * Cz;

    // 0. split weights to hi/lo bf16
    struct WS { const float* src; int off; int n; };
    WS ws[10] = {
        { Wr, O_Wr, Cz*Cz }, { Wk, O_Wk, Cz*Cz }, { Wv, O_Wv, Cz*Cz }, { Wo, O_Wo, Cz*Cz },
        { w1, O_w1, Cz*64 }, { w2, O_w2, 64*Cz }, { a1, O_a1, Cz*64 }, { a2, O_a2, 64*Cz },
        { g1, O_g1, Cz*128 }, { g2, O_g2, 128*Cz },
    };
    for (int i = 0; i < 10; i++) {
        int n4 = ws[i].n / 4;
        split_kernel<<<(n4 + 255)/256, 256>>>(ws[i].src, wh + ws[i].off, wl + ws[i].off, n4);
    }

    // 1. token shift + mix -> hi/lo streams (r=0,w=1,k=2,v=3,a=4,g=5)
    mix_kernel<<<(BTz*Cz/4 + 255)/256, 256>>>(x, x_r, x_w, x_k, x_v, x_a, x_g, xh, xl);

    dim3 bg(Cz/128, BTz/128);

    // 2. big projections (bf16x3 tensor)
    mma_gemm<128,128,32,64,32,0,0><<<bg, 256>>>(BTz, Cz, Cz, xh + 0*S, xl + 0*S,
        wh + O_Wr, wl + O_Wr, rb, nullptr, nullptr, nullptr);
    mma_gemm<128,128,32,64,32,0,0><<<bg, 256>>>(BTz, Cz, Cz, xh + 2*S, xl + 2*S,
        wh + O_Wk, wl + O_Wk, kb, nullptr, nullptr, nullptr);
    mma_gemm<128,128,32,64,32,0,0><<<bg, 256>>>(BTz, Cz, Cz, xh + 3*S, xl + 3*S,
        wh + O_Wv, wl + O_Wv, vb, nullptr, nullptr, nullptr);

    // 3. decay LoRA: h = tanh(xw@w1) (split out); wd = decay(w0 + h@w2)
    mma_gemm<128,64,32,64,32,1,1><<<dim3(1, BTz/128), 128>>>(BTz, 64, Cz, xh + 1*S, xl + 1*S,
        wh + O_w1, wl + O_w1, nullptr, hh, hl, nullptr);
    mma_gemm<128,128,32,64,32,3,0><<<bg, 256>>>(BTz, Cz, 64, hh, hl,
        wh + O_w2, wl + O_w2, wd, nullptr, nullptr, w0);

    // 4. a LoRA: h = xa@a1 (split); a = sigmoid(a0 + h@a2)
    mma_gemm<128,64,32,64,32,0,1><<<dim3(1, BTz/128), 128>>>(BTz, 64, Cz, xh + 4*S, xl + 4*S,
        wh + O_a1, wl + O_a1, nullptr, hh, hl, nullptr);
    mma_gemm<128,128,32,64,32,2,0><<<bg, 256>>>(BTz, Cz, 64, hh, hl,
        wh + O_a2, wl + O_a2, ab, nullptr, nullptr, a0);

    // 5. g LoRA: h = sigmoid(xg@g1) (split); g = h@g2
    mma_gemm<128,128,32,64,32,2,1><<<dim3(1, BTz/128), 256>>>(BTz, 128, Cz, xh + 5*S, xl + 5*S,
        wh + O_g1, wl + O_g1, nullptr, hh, hl, nullptr);
    mma_gemm<128,128,32,64,32,0,0><<<bg, 256>>>(BTz, Cz, 128, hh, hl,
        wh + O_g2, wl + O_g2, gb, nullptr, nullptr, nullptr);

    // 6. kk normalize / aa / bb / k update
    prep_kernel<<<BTz*Hz/8, 256>>>(k_k, k_a);

    // 7. sequential scan
    scan_kernel<<<Bz*Hz, 128>>>(rb, wd, kb, aab, bbb, vb, ob);

    // 8. groupnorm + bonus + gate -> yg hi/lo
    post_kernel<<<BTz*Hz/8, 256>>>(r_k, lg, lb);

    // 9. output projection
    mma_gemm<128,128,32,64,32,0,0><<<bg, 256>>>(BTz, Cz, Cz, ygh, ygl,
        wh + O_Wo, wl + O_Wo, (float*)d_out, nullptr, nullptr, nullptr);

    // 10. v_first if expected
    if (out_size >= 2 * BTz * Cz) {
        cudaMemcpyAsync((float*)d_out + S, vb, sizeof(float) * S, cudaMemcpyDeviceToDevice);
    }
}

// round 5
// speedup vs baseline: 1.3873x; 1.1103x over previous
#include <cuda_runtime.h>
#include <cuda_bf16.h>
#include <cstdint>
#include <math.h>

#define Bz   4
#define Tz   1024
#define Cz   1024
#define Hz   16
#define BTz  (Bz*Tz)

typedef __nv_bfloat16  bf16;
typedef __nv_bfloat162 bf162;
typedef unsigned long long u64;

// ---------------- scratch (device globals; no allocation allowed) ----------------
__device__ float g_r [BTz*Cz], g_k [BTz*Cz], g_v [BTz*Cz], g_wd[BTz*Cz];
__device__ float g_a [BTz*Cz], g_g [BTz*Cz], g_aa[BTz*Cz], g_bb[BTz*Cz], g_o [BTz*Cz];

__device__ bf16 g_xh[6*BTz*Cz], g_xl[6*BTz*Cz];      // mixed streams hi/lo (r,w,k,v,a,g)
__device__ bf16 g_ygh[BTz*Cz],  g_ygl[BTz*Cz];       // (gn(o)+bonus)*g hi/lo
// LoRA hidden pool: decay(64) @ 0, a(64) @ BTz*64, g(128) @ BTz*128  -> BTz*256 total
#define HID_A (BTz*64)
#define HID_G (BTz*128)
__device__ bf16 g_hh[BTz*256],  g_hl[BTz*256];

#define O_Wr 0
#define O_Wk (Cz*Cz)
#define O_Wv (2*Cz*Cz)
#define O_Wo (3*Cz*Cz)
#define O_w1 (4*Cz*Cz)
#define O_w2 (O_w1 + Cz*64)
#define O_a1 (O_w2 + 64*Cz)
#define O_a2 (O_a1 + Cz*64)
#define O_g1 (O_a2 + 64*Cz)
#define O_g2 (O_g1 + Cz*128)
#define WPOOL (O_g2 + 128*Cz)
__device__ bf16 g_wh[WPOOL], g_wl[WPOOL];

// ---------------- small helpers ----------------
__device__ __forceinline__ uint32_t su32(const void* p) {
    return (uint32_t)__cvta_generic_to_shared(p);
}
__device__ __forceinline__ void ldsm4(uint32_t& a0, uint32_t& a1, uint32_t& a2, uint32_t& a3, uint32_t addr) {
    asm volatile("ldmatrix.sync.aligned.m8n8.x4.shared.b16 {%0,%1,%2,%3},[%4];"
                 : "=r"(a0), "=r"(a1), "=r"(a2), "=r"(a3) : "r"(addr));
}
__device__ __forceinline__ void ldsm4t(uint32_t& a0, uint32_t& a1, uint32_t& a2, uint32_t& a3, uint32_t addr) {
    asm volatile("ldmatrix.sync.aligned.m8n8.x4.trans.shared.b16 {%0,%1,%2,%3},[%4];"
                 : "=r"(a0), "=r"(a1), "=r"(a2), "=r"(a3) : "r"(addr));
}
__device__ __forceinline__ void mma16816(float* c, const uint32_t* a, const uint32_t* b) {
    asm volatile("mma.sync.aligned.m16n8k16.row.col.f32.bf16.bf16.f32 "
                 "{%0,%1,%2,%3},{%4,%5,%6,%7},{%8,%9},{%0,%1,%2,%3};"
                 : "+f"(c[0]), "+f"(c[1]), "+f"(c[2]), "+f"(c[3])
                 : "r"(a[0]), "r"(a[1]), "r"(a[2]), "r"(a[3]), "r"(b[0]), "r"(b[1]));
}
__device__ __forceinline__ void cpa16(uint32_t dst, const void* src) {
    asm volatile("cp.async.ca.shared.global [%0], [%1], 16;" :: "r"(dst), "l"(src));
}
__device__ __forceinline__ void cpa_commit() { asm volatile("cp.async.commit_group;"); }
template<int NN> __device__ __forceinline__ void cpa_wait() { asm volatile("cp.async.wait_group %0;" :: "n"(NN)); }

// packed f32x2 (Blackwell)
__device__ __forceinline__ u64 ffma2(u64 a, u64 b, u64 c) {
    u64 d; asm("fma.rn.f32x2 %0,%1,%2,%3;" : "=l"(d) : "l"(a), "l"(b), "l"(c)); return d;
}
__device__ __forceinline__ u64 fmul2(u64 a, u64 b) {
    u64 d; asm("mul.rn.f32x2 %0,%1,%2;" : "=l"(d) : "l"(a), "l"(b)); return d;
}
__device__ __forceinline__ u64 pack2(float x, float y) {
    u64 d; asm("mov.b64 %0,{%1,%2};" : "=l"(d) : "f"(x), "f"(y)); return d;
}
__device__ __forceinline__ float2 unpack2(u64 a) {
    float x, y; asm("mov.b64 {%0,%1},%2;" : "=f"(x), "=f"(y) : "l"(a)); return make_float2(x, y);
}

__device__ __forceinline__ void pack_hl(float4 o, uint2& h, uint2& l) {
    bf162 h0 = __floats2bfloat162_rn(o.x, o.y);
    bf162 h1 = __floats2bfloat162_rn(o.z, o.w);
    h.x = *(uint32_t*)&h0;  h.y = *(uint32_t*)&h1;
    bf162 l0 = __floats2bfloat162_rn(o.x - __bfloat162float(h0.x), o.y - __bfloat162float(h0.y));
    bf162 l1 = __floats2bfloat162_rn(o.z - __bfloat162float(h1.x), o.w - __bfloat162float(h1.y));
    l.x = *(uint32_t*)&l0;  l.y = *(uint32_t*)&l1;
}

// ---------------- fused weight split fp32 -> bf16 hi/lo pool ----------------
struct SplitJobs { const float* src[10]; int cum[11]; };

__global__ void split_all_kernel(SplitJobs jobs, bf16* __restrict__ hi, bf16* __restrict__ lo)
{
    int i = blockIdx.x * blockDim.x + threadIdx.x;       // float4 index
    if (i >= WPOOL / 4) return;
    int e = i * 4;
    int s = 0;
#pragma unroll
    for (int j = 1; j < 10; j++) if (e >= jobs.cum[j]) s = j;
    float4 v = *(const float4*)(jobs.src[s] + (e - jobs.cum[s]));
    uint2 h, l;
    pack_hl(v, h, l);
    ((uint2*)hi)[i] = h;
    ((uint2*)lo)[i] = l;
}

// ---------------- token shift + 6-way mix, emitting hi/lo bf16 ----------------
__global__ void mix_kernel(const float* __restrict__ x,
                           const float* __restrict__ mr, const float* __restrict__ mw,
                           const float* __restrict__ mk, const float* __restrict__ mv,
                           const float* __restrict__ ma, const float* __restrict__ mg,
                           bf16* __restrict__ xh, bf16* __restrict__ xl)
{
    int idx = blockIdx.x * blockDim.x + threadIdx.x;     // float4 index
    const int total = BTz * Cz / 4;
    if (idx >= total) return;
    int c4 = idx % (Cz / 4);
    int bt = idx / (Cz / 4);
    int t  = bt % Tz;
    const float4* x4 = (const float4*)x;
    float4 cur = x4[idx];
    float4 prev = make_float4(0.f, 0.f, 0.f, 0.f);
    if (t > 0) prev = x4[idx - Cz / 4];
    float4 xx = make_float4(prev.x - cur.x, prev.y - cur.y, prev.z - cur.z, prev.w - cur.w);
    int c = c4 * 4;
    const float* ms[6] = { mr, mw, mk, mv, ma, mg };
#pragma unroll
    for (int s = 0; s < 6; s++) {
        float4 mm = *(const float4*)(ms[s] + c);
        float4 o;
        o.x = cur.x + xx.x * mm.x;  o.y = cur.y + xx.y * mm.y;
        o.z = cur.z + xx.z * mm.z;  o.w = cur.w + xx.w * mm.w;
        uint2 h, l;
        pack_hl(o, h, l);
        ((uint2*)(xh + (size_t)s * BTz * Cz))[idx] = h;
        ((uint2*)(xl + (size_t)s * BTz * Cz))[idx] = l;
    }
}

// ---------------- epilogues ----------------
template<int EPI>
__device__ __forceinline__ float apply_epi(float acc, float b)
{
    float pre = acc + b;
    if (EPI == 0) return pre;
    if (EPI == 1) return tanhf(pre);
    if (EPI == 2) return 1.f / (1.f + expf(-pre));
    float sp = (pre > -30.f) ? log1pf(expf(-pre)) : -pre;   // softplus(-pre)
    return expf(-expf(-sp - 0.5f));
}

// ---------------- bf16x3 tensor-core GEMM, cp.async 2-stage pipelined ----------------
// C = Ah*Bh + Ah*Bl + Al*Bh.  A row-major [M,K], B row-major [K,N].
// OUT: 0 -> fp32 C, 1 -> hi/lo bf16 Ch/Cl.
template<int BM, int BN, int WM, int WN, int EPI, int OUT>
__global__ __launch_bounds__((BM/WM)*(BN/WN)*32)
void mma_gemm(int M, int N, int K,
              const bf16* __restrict__ Ah, const bf16* __restrict__ Al,
              const bf16* __restrict__ Bh, const bf16* __restrict__ Bl,
              float* __restrict__ C, bf16* __restrict__ Ch, bf16* __restrict__ Cl,
              const float* __restrict__ bias)
{
    constexpr int BK = 16;
    constexpr int WARPS  = (BM/WM)*(BN/WN);
    constexpr int THREADS = WARPS * 32;
    constexpr int MFR = WM / 16, NFR = WN / 8;
    constexpr int AKp = BK + 8;            // padded strides (halves)
    constexpr int BNp = BN + 8;
    constexpr int ASTG = 2 * BM * AKp;     // halves per stage (2 planes)
    constexpr int BSTG = 2 * BK * BNp;
    __shared__ __align__(16) bf16 sA[2 * ASTG];
    __shared__ __align__(16) bf16 sB[2 * BSTG];

    const int tid = threadIdx.x, lane = tid & 31, warp = tid >> 5;
    const int wN = warp % (BN/WN), wM = warp / (BN/WN);
    const int row0 = blockIdx.y * BM, col0 = blockIdx.x * BN;

    float acc[MFR][NFR][4];
#pragma unroll
    for (int i = 0; i < MFR; i++)
#pragma unroll
        for (int j = 0; j < NFR; j++)
#pragma unroll
            for (int q = 0; q < 4; q++) acc[i][j][q] = 0.f;

    const uint32_t sAu = su32(sA), sBu = su32(sB);
    uint32_t aBase[MFR], bBase[NFR/2];
#pragma unroll
    for (int fm = 0; fm < MFR; fm++)
        aBase[fm] = sAu + ((wM*WM + fm*16 + (lane & 15)) * AKp + ((lane >> 4) * 8)) * 2;
#pragma unroll
    for (int p = 0; p < NFR/2; p++)
        bBase[p] = sBu + ((lane & 15) * BNp + wN*WN + p*16 + ((lane >> 4) * 8)) * 2;

    constexpr uint32_t A_LO = BM * AKp * 2;   // byte offset hi-plane -> lo-plane
    constexpr uint32_t B_LO = BK * BNp * 2;

    const int T = K / BK;

    // ---- tile loader via cp.async ----
    auto load_tile = [&](int stg, int k0) {
        for (int i = tid; i < 2 * BM * (BK/8); i += THREADS) {
            int p = (i >= BM * (BK/8));
            int j = p ? i - BM * (BK/8) : i;
            int r = j / (BK/8), c = (j % (BK/8)) * 8;
            const bf16* src = (p ? Al : Ah) + (size_t)(row0 + r) * K + k0 + c;
            cpa16(sAu + (stg * ASTG + p * BM * AKp + r * AKp + c) * 2, src);
        }
        for (int i = tid; i < 2 * BK * (BN/8); i += THREADS) {
            int p = (i >= BK * (BN/8));
            int j = p ? i - BK * (BN/8) : i;
            int r = j / (BN/8), c = (j % (BN/8)) * 8;
            const bf16* src = (p ? Bl : Bh) + (size_t)(k0 + r) * N + col0 + c;
            cpa16(sBu + (stg * BSTG + p * BK * BNp + r * BNp + c) * 2, src);
        }
    };

    load_tile(0, 0);
    cpa_commit();

    for (int t = 0; t < T; t++) {
        if (t + 1 < T) { load_tile((t + 1) & 1, (t + 1) * BK); cpa_commit(); cpa_wait<1>(); }
        else cpa_wait<0>();
        __syncthreads();

        const uint32_t aOff = (t & 1) * ASTG * 2;
        const uint32_t bOff = (t & 1) * BSTG * 2;
        uint32_t Afh[MFR][4], Afl[MFR][4], Bfh[NFR][2], Bfl[NFR][2];
#pragma unroll
        for (int fm = 0; fm < MFR; fm++) {
            ldsm4(Afh[fm][0], Afh[fm][1], Afh[fm][2], Afh[fm][3], aBase[fm] + aOff);
            ldsm4(Afl[fm][0], Afl[fm][1], Afl[fm][2], Afl[fm][3], aBase[fm] + aOff + A_LO);
        }
#pragma unroll
        for (int p = 0; p < NFR/2; p++) {
            uint32_t t0, t1, t2, t3;
            ldsm4t(t0, t1, t2, t3, bBase[p] + bOff);
            Bfh[2*p][0] = t0; Bfh[2*p][1] = t1; Bfh[2*p+1][0] = t2; Bfh[2*p+1][1] = t3;
            ldsm4t(t0, t1, t2, t3, bBase[p] + bOff + B_LO);
            Bfl[2*p][0] = t0; Bfl[2*p][1] = t1; Bfl[2*p+1][0] = t2; Bfl[2*p+1][1] = t3;
        }
#pragma unroll
        for (int fm = 0; fm < MFR; fm++)
#pragma unroll
            for (int fn = 0; fn < NFR; fn++) {
                mma16816(acc[fm][fn], Afh[fm], Bfh[fn]);
                mma16816(acc[fm][fn], Afh[fm], Bfl[fn]);
                mma16816(acc[fm][fn], Afl[fm], Bfh[fn]);
            }
        __syncthreads();
    }

#pragma unroll
    for (int fm = 0; fm < MFR; fm++) {
        int r = row0 + wM*WM + fm*16 + (lane >> 2);
#pragma unroll
        for (int fn = 0; fn < NFR; fn++) {
            int c = col0 + wN*WN + fn*8 + 2*(lane & 3);
            float b0 = bias ? bias[c] : 0.f;
            float b1 = bias ? bias[c+1] : 0.f;
            float x0 = apply_epi<EPI>(acc[fm][fn][0], b0);
            float x1 = apply_epi<EPI>(acc[fm][fn][1], b1);
            float x2 = apply_epi<EPI>(acc[fm][fn][2], b0);
            float x3 = apply_epi<EPI>(acc[fm][fn][3], b1);
            if (OUT == 0) {
                *(float2*)&C[(size_t)r*N + c]     = make_float2(x0, x1);
                *(float2*)&C[(size_t)(r+8)*N + c] = make_float2(x2, x3);
            } else {
                bf162 h0 = __floats2bfloat162_rn(x0, x1);
                bf162 h1 = __floats2bfloat162_rn(x2, x3);
                *(bf162*)&Ch[(size_t)r*N + c]     = h0;
                *(bf162*)&Ch[(size_t)(r+8)*N + c] = h1;
                bf162 l0 = __floats2bfloat162_rn(x0 - __bfloat162float(h0.x), x1 - __bfloat162float(h0.y));
                bf162 l1 = __floats2bfloat162_rn(x2 - __bfloat162float(h1.x), x3 - __bfloat162float(h1.y));
                *(bf162*)&Cl[(size_t)r*N + c]     = l0;
                *(bf162*)&Cl[(size_t)(r+8)*N + c] = l1;
            }
        }
    }
}

// ---------------- kk normalize, aa, bb, k update ----------------
__global__ void prep_kernel(const float* __restrict__ kkw, const float* __restrict__ kaw)
{
    int gw   = (blockIdx.x * blockDim.x + threadIdx.x) >> 5;
    int lane = threadIdx.x & 31;
    if (gw >= BTz * Hz) return;
    int bt = gw / Hz, h = gw % Hz;
    int c0 = h * 64 + lane, c1 = c0 + 32;
    size_t base = (size_t)bt * Cz;
    float k0 = g_k[base + c0], k1 = g_k[base + c1];
    float kk0 = k0 * kkw[c0], kk1 = k1 * kkw[c1];
    float ss = kk0*kk0 + kk1*kk1;
#pragma unroll
    for (int m = 16; m > 0; m >>= 1) ss += __shfl_xor_sync(0xffffffffu, ss, m);
    float inv = 1.f / fmaxf(sqrtf(ss), 1e-12f);
    float a0 = g_a[base + c0], a1v = g_a[base + c1];
    kk0 *= inv; kk1 *= inv;
    g_aa[base + c0] = -kk0;       g_aa[base + c1] = -kk1;
    g_bb[base + c0] = kk0 * a0;   g_bb[base + c1] = kk1 * a1v;
    g_k [base + c0] = k0 * (1.f + (a0  - 1.f) * kaw[c0]);
    g_k [base + c1] = k1 * (1.f + (a1v - 1.f) * kaw[c1]);
}

// ---------------- sequential RWKV7 state scan (f32x2 packed, 256 thr) ----------------
// tid = i*4 + jq; thread owns S[i][jq*16 .. jq*16+15] as 8 packed f32x2.
__global__ __launch_bounds__(256)
void scan_kernel(const float* __restrict__ r, const float* __restrict__ wdec,
                 const float* __restrict__ k, const float* __restrict__ aa,
                 const float* __restrict__ bb, const float* __restrict__ v,
                 float* __restrict__ o)
{
    const int bh = blockIdx.x;
    const int b = bh / Hz, h = bh % Hz;
    const int tid = threadIdx.x;
    const int i  = tid >> 2;
    const int jq = tid & 3;
    const int jb = jq * 16;

    __shared__ __align__(16) float sm[2][6*64];   // r,w,k,aa,bb,v @ stride 64
    u64 S2[8];
#pragma unroll
    for (int q = 0; q < 8; q++) S2[q] = 0ULL;

    const size_t base = (size_t)b * Tz * Cz + h * 64;
    const float* vp[6] = { r + base, wdec + base, k + base, aa + base, bb + base, v + base };

    // prefetch slots: u=0 -> lin = tid (vec 0..3); u=1 -> lin = 256+tid (tid<128, vec 4..5)
    const float* myp[2]; int mys[2]; int nslot = (tid < 128) ? 2 : 1;
#pragma unroll
    for (int u = 0; u < 2; u++) {
        int lin = u * 256 + tid;
        if (lin >= 384) lin = 0;
        int vec = lin >> 6;
        int idx = lin & 63;
        const float* p = vp[0];
        if (vec == 1) p = vp[1]; else if (vec == 2) p = vp[2];
        else if (vec == 3) p = vp[3]; else if (vec == 4) p = vp[4];
        else if (vec == 5) p = vp[5];
        myp[u] = p + idx;
        mys[u] = lin;
    }

    for (int u = 0; u < nslot; u++) sm[0][mys[u]] = myp[u][0];
    __syncthreads();

    float* obase = o + base;
    for (int t = 0; t < Tz; t++) {
        const int cur = t & 1;
        if (t + 1 < Tz) {
            size_t off = (size_t)(t + 1) * Cz;
            for (int u = 0; u < nslot; u++) sm[cur ^ 1][mys[u]] = myp[u][off];
        }
        const float* s_r  = &sm[cur][0];
        const float* s_w  = &sm[cur][64];
        const float* s_k  = &sm[cur][128];
        const float* s_aa = &sm[cur][192];
        const float* s_bb = &sm[cur][256];
        const float* s_v  = &sm[cur][320];

        // sa = S @ aa (partial over 16 cols, packed)
        u64 p0 = 0ULL, p1 = 0ULL;
#pragma unroll
        for (int g = 0; g < 4; g++) {
            ulonglong2 a2 = *(const ulonglong2*)&s_aa[jb + 4*g];
            p0 = ffma2(S2[2*g],   a2.x, p0);
            p1 = ffma2(S2[2*g+1], a2.y, p1);
        }
        float2 f0 = unpack2(p0), f1 = unpack2(p1);
        float sa = (f0.x + f0.y) + (f1.x + f1.y);
        sa += __shfl_xor_sync(0xffffffffu, sa, 1);
        sa += __shfl_xor_sync(0xffffffffu, sa, 2);
        const u64 sa2 = pack2(sa, sa);
        const float vi = s_v[i];
        const u64 vi2 = pack2(vi, vi);

        // S = S*w + sa*bb + vi*k ; out = S @ r (partial)
        u64 o0 = 0ULL, o1 = 0ULL;
#pragma unroll
        for (int g = 0; g < 4; g++) {
            ulonglong2 w2 = *(const ulonglong2*)&s_w [jb + 4*g];
            ulonglong2 b2 = *(const ulonglong2*)&s_bb[jb + 4*g];
            ulonglong2 k2 = *(const ulonglong2*)&s_k [jb + 4*g];
            ulonglong2 r2 = *(const ulonglong2*)&s_r [jb + 4*g];
            S2[2*g]   = ffma2(S2[2*g],   w2.x, ffma2(sa2, b2.x, fmul2(vi2, k2.x)));
            o0        = ffma2(S2[2*g],   r2.x, o0);
            S2[2*g+1] = ffma2(S2[2*g+1], w2.y, ffma2(sa2, b2.y, fmul2(vi2, k2.y)));
            o1        = ffma2(S2[2*g+1], r2.y, o1);
        }
        float2 q0 = unpack2(o0), q1 = unpack2(o1);
        float out = (q0.x + q0.y) + (q1.x + q1.y);
        out += __shfl_xor_sync(0xffffffffu, out, 1);
        out += __shfl_xor_sync(0xffffffffu, out, 2);
        if (jq == 0) obase[(size_t)t * Cz + i] = out;
        __syncthreads();
    }
}

// ---------------- groupnorm + rk bonus + gate -> hi/lo bf16 ----------------
__global__ void post_kernel(const float* __restrict__ rk,
                            const float* __restrict__ gamma, const float* __restrict__ beta)
{
    int gw   = (blockIdx.x * blockDim.x + threadIdx.x) >> 5;
    int lane = threadIdx.x & 31;
    if (gw >= BTz * Hz) return;
    int bt = gw / Hz, h = gw % Hz;
    int c0 = h * 64 + lane, c1 = c0 + 32;
    size_t base = (size_t)bt * Cz;
    float o0 = g_o[base + c0], o1 = g_o[base + c1];
    float s1 = o0 + o1;
    float s2 = o0*o0 + o1*o1;
    float r0 = g_r[base + c0], r1 = g_r[base + c1];
    float k0 = g_k[base + c0], k1 = g_k[base + c1];
    float bon = r0 * k0 * rk[h * 64 + lane] + r1 * k1 * rk[h * 64 + lane + 32];
#pragma unroll
    for (int m = 16; m > 0; m >>= 1) {
        s1  += __shfl_xor_sync(0xffffffffu, s1,  m);
        s2  += __shfl_xor_sync(0xffffffffu, s2,  m);
        bon += __shfl_xor_sync(0xffffffffu, bon, m);
    }
    float mu   = s1 * (1.f / 64.f);
    float var  = s2 * (1.f / 64.f) - mu * mu;
    float rstd = rsqrtf(var + 0.00064f);
    float v0 = g_v[base + c0], v1 = g_v[base + c1];
    float y0 = ((o0 - mu) * rstd * gamma[c0] + beta[c0] + bon * v0) * g_g[base + c0];
    float y1 = ((o1 - mu) * rstd * gamma[c1] + beta[c1] + bon * v1) * g_g[base + c1];
    bf16 h0 = __float2bfloat16_rn(y0);
    bf16 h1 = __float2bfloat16_rn(y1);
    g_ygh[base + c0] = h0;  g_ygh[base + c1] = h1;
    g_ygl[base + c0] = __float2bfloat16_rn(y0 - __bfloat162float(h0));
    g_ygl[base + c1] = __float2bfloat16_rn(y1 - __bfloat162float(h1));
}

// ---------------- launch ----------------
extern "C" void kernel_launch(void* const* d_in, const int* in_sizes, int n_in,
                              void* d_out, int out_size)
{
    const float* x    = (const float*)d_in[0];
    const float* x_r  = (const float*)d_in[1];
    const float* x_w  = (const float*)d_in[2];
    const float* x_k  = (const float*)d_in[3];
    const float* x_v  = (const float*)d_in[4];
    const float* x_a  = (const float*)d_in[5];
    const float* x_g  = (const float*)d_in[6];
    const float* w0   = (const float*)d_in[7];
    const float* w1   = (const float*)d_in[8];
    const float* w2   = (const float*)d_in[9];
    const float* a0   = (const float*)d_in[10];
    const float* a1   = (const float*)d_in[11];
    const float* a2   = (const float*)d_in[12];
    const float* g1   = (const float*)d_in[16];
    const float* g2   = (const float*)d_in[17];
    const float* k_k  = (const float*)d_in[18];
    const float* k_a  = (const float*)d_in[19];
    const float* r_k  = (const float*)d_in[20];
    const float* Wr   = (const float*)d_in[21];
    const float* Wk   = (const float*)d_in[22];
    const float* Wv   = (const float*)d_in[23];
    const float* Wo   = (const float*)d_in[24];
    const float* lg   = (const float*)d_in[25];
    const float* lb   = (const float*)d_in[26];

    void *pr, *pk, *pv, *pwd, *pa, *pg, *paa, *pbb, *po;
    void *pxh, *pxl, *pygh, *pygl, *phh, *phl, *pwh, *pwl;
    cudaGetSymbolAddress(&pr,  g_r);   cudaGetSymbolAddress(&pk,  g_k);
    cudaGetSymbolAddress(&pv,  g_v);   cudaGetSymbolAddress(&pwd, g_wd);
    cudaGetSymbolAddress(&pa,  g_a);   cudaGetSymbolAddress(&pg,  g_g);
    cudaGetSymbolAddress(&paa, g_aa);  cudaGetSymbolAddress(&pbb, g_bb);
    cudaGetSymbolAddress(&po,  g_o);
    cudaGetSymbolAddress(&pxh, g_xh);  cudaGetSymbolAddress(&pxl, g_xl);
    cudaGetSymbolAddress(&pygh, g_ygh); cudaGetSymbolAddress(&pygl, g_ygl);
    cudaGetSymbolAddress(&phh, g_hh);  cudaGetSymbolAddress(&phl, g_hl);
    cudaGetSymbolAddress(&pwh, g_wh);  cudaGetSymbolAddress(&pwl, g_wl);

    float *rb = (float*)pr, *kb = (float*)pk, *vb = (float*)pv, *wd = (float*)pwd;
    float *ab = (float*)pa, *gb = (float*)pg, *aab = (float*)paa, *bbb = (float*)pbb;
    float *ob = (float*)po;
    bf16 *xh = (bf16*)pxh, *xl = (bf16*)pxl;
    bf16 *ygh = (bf16*)pygh, *ygl = (bf16*)pygl;
    bf16 *hh = (bf16*)phh, *hl = (bf16*)phl;
    bf16 *wh = (bf16*)pwh, *wl = (bf16*)pwl;

    const size_t S = (size_t)BTz * Cz;

    // 1. fused weight split (one launch)
    SplitJobs jobs;
    jobs.src[0] = Wr;  jobs.src[1] = Wk;  jobs.src[2] = Wv;  jobs.src[3] = Wo;
    jobs.src[4] = w1;  jobs.src[5] = w2;  jobs.src[6] = a1;  jobs.src[7] = a2;
    jobs.src[8] = g1;  jobs.src[9] = g2;
    jobs.cum[0] = O_Wr; jobs.cum[1] = O_Wk; jobs.cum[2] = O_Wv; jobs.cum[3] = O_Wo;
    jobs.cum[4] = O_w1; jobs.cum[5] = O_w2; jobs.cum[6] = O_a1; jobs.cum[7] = O_a2;
    jobs.cum[8] = O_g1; jobs.cum[9] = O_g2; jobs.cum[10] = WPOOL;
    split_all_kernel<<<(WPOOL/4 + 255)/256, 256>>>(jobs, wh, wl);

    // 2. token shift + mix -> hi/lo streams (r=0,w=1,k=2,v=3,a=4,g=5)
    mix_kernel<<<(BTz*Cz/4 + 255)/256, 256>>>(x, x_r, x_w, x_k, x_v, x_a, x_g, xh, xl);

    dim3 bg(Cz/128, BTz/128);

    // 3-5. LoRA stage-1 (launches 3..5 so that launch 6 = big GEMM for ncu)
    mma_gemm<128,64,64,32,1,1><<<dim3(1, BTz/128), 128>>>(BTz, 64, Cz, xh + 1*S, xl + 1*S,
        wh + O_w1, wl + O_w1, nullptr, hh, hl, nullptr);                       // tanh(xw@w1)
    mma_gemm<128,64,64,32,0,1><<<dim3(1, BTz/128), 128>>>(BTz, 64, Cz, xh + 4*S, xl + 4*S,
        wh + O_a1, wl + O_a1, nullptr, hh + HID_A, hl + HID_A, nullptr);       // xa@a1
    mma_gemm<128,128,64,32,2,1><<<dim3(1, BTz/128), 256>>>(BTz, 128, Cz, xh + 5*S, xl + 5*S,
        wh + O_g1, wl + O_g1, nullptr, hh + HID_G, hl + HID_G, nullptr);       // sigmoid(xg@g1)

    // 6-8. big projections (launch 6 profiled)
    mma_gemm<128,128,64,32,0,0><<<bg, 256>>>(BTz, Cz, Cz, xh + 0*S, xl + 0*S,
        wh + O_Wr, wl + O_Wr, rb, nullptr, nullptr, nullptr);
    mma_gemm<128,128,64,32,0,0><<<bg, 256>>>(BTz, Cz, Cz, xh + 2*S, xl + 2*S,
        wh + O_Wk, wl + O_Wk, kb, nullptr, nullptr, nullptr);
    mma_gemm<128,128,64,32,0,0><<<bg, 256>>>(BTz, Cz, Cz, xh + 3*S, xl + 3*S,
        wh + O_Wv, wl + O_Wv, vb, nullptr, nullptr, nullptr);

    // 9-11. LoRA stage-2
    mma_gemm<128,128,64,32,3,0><<<bg, 256>>>(BTz, Cz, 64, hh, hl,
        wh + O_w2, wl + O_w2, wd, nullptr, nullptr, w0);                       // decay
    mma_gemm<128,128,64,32,2,0><<<bg, 256>>>(BTz, Cz, 64, hh + HID_A, hl + HID_A,
        wh + O_a2, wl + O_a2, ab, nullptr, nullptr, a0);                       // a
    mma_gemm<128,128,64,32,0,0><<<bg, 256>>>(BTz, Cz, 128, hh + HID_G, hl + HID_G,
        wh + O_g2, wl + O_g2, gb, nullptr, nullptr, nullptr);                  // g

    // 12. kk normalize / aa / bb / k update
    prep_kernel<<<BTz*Hz/8, 256>>>(k_k, k_a);

    // 13. sequential scan
    scan_kernel<<<Bz*Hz, 256>>>(rb, wd, kb, aab, bbb, vb, ob);

    // 14. groupnorm + bonus + gate -> yg hi/lo
    post_kernel<<<BTz*Hz/8, 256>>>(r_k, lg, lb);

    // 15. output projection
    mma_gemm<128,128,64,32,0,0><<<bg, 256>>>(BTz, Cz, Cz, ygh, ygl,
        wh + O_Wo, wl + O_Wo, (float*)d_out, nullptr, nullptr, nullptr);

    // 16. v_first if expected
    if (out_size >= 2 * BTz * Cz) {
        cudaMemcpyAsync((float*)d_out + S, vb, sizeof(float) * S, cudaMemcpyDeviceToDevice);
    }
}

// round 8
// speedup vs baseline: 1.5282x; 1.1016x over previous
#include <cuda_runtime.h>
#include <cuda.h>
#include <cuda_bf16.h>
#include <cstdint>
#include <math.h>

#define Bz   4
#define Tz   1024
#define Cz   1024
#define Hz   16
#define BTz  (Bz*Tz)

typedef __nv_bfloat16  bf16;
typedef __nv_bfloat162 bf162;
typedef unsigned long long u64;

// ---------------- scratch (device globals; no allocation allowed) ----------------
__device__ float g_r [BTz*Cz], g_k [BTz*Cz], g_v [BTz*Cz], g_wd[BTz*Cz];
__device__ float g_a [BTz*Cz], g_g [BTz*Cz], g_aa[BTz*Cz], g_bb[BTz*Cz], g_o [BTz*Cz];

__device__ __align__(256) bf16 g_xh[6*BTz*Cz], g_xl[6*BTz*Cz];   // mixed streams hi/lo
__device__ __align__(256) bf16 g_ygh[BTz*Cz],  g_ygl[BTz*Cz];    // (gn(o)+bonus)*g hi/lo
// LoRA hidden pool [BTz, 256]: cols 0-63 decay, 64-127 a, 128-255 g
__device__ __align__(256) bf16 g_hh[BTz*256],  g_hl[BTz*256];

// weight pool: all matrices stored TRANSPOSED [N, K] row-major, bf16 hi/lo
#define O_Wr 0
#define O_Wk (Cz*Cz)
#define O_Wv (2*Cz*Cz)
#define O_Wo (3*Cz*Cz)
#define O_L1 (4*Cz*Cz)                  // [256, 1024]: w1t 0-63, a1t 64-127, g1t 128-255
#define O_W2T (O_L1 + 256*Cz)           // [1024, 64]
#define O_A2T (O_W2T + Cz*64)           // [1024, 64]
#define O_G2T (O_A2T + Cz*64)           // [1024, 128]
#define WPOOL (O_G2T + Cz*128)
__device__ __align__(256) bf16 g_wh[WPOOL], g_wl[WPOOL];

// ---------------- helpers ----------------
__device__ __forceinline__ uint32_t su32(const void* p) {
    return (uint32_t)__cvta_generic_to_shared(p);
}
__device__ __forceinline__ void ldsm4(uint32_t& a0, uint32_t& a1, uint32_t& a2, uint32_t& a3, uint32_t addr) {
    asm volatile("ldmatrix.sync.aligned.m8n8.x4.shared.b16 {%0,%1,%2,%3},[%4];"
                 : "=r"(a0), "=r"(a1), "=r"(a2), "=r"(a3) : "r"(addr));
}
__device__ __forceinline__ void mma16816(float* c, const uint32_t* a, const uint32_t* b) {
    asm volatile("mma.sync.aligned.m16n8k16.row.col.f32.bf16.bf16.f32 "
                 "{%0,%1,%2,%3},{%4,%5,%6,%7},{%8,%9},{%0,%1,%2,%3};"
                 : "+f"(c[0]), "+f"(c[1]), "+f"(c[2]), "+f"(c[3])
                 : "r"(a[0]), "r"(a[1]), "r"(a[2]), "r"(a[3]), "r"(b[0]), "r"(b[1]));
}
__device__ __forceinline__ u64 ffma2(u64 a, u64 b, u64 c) {
    u64 d; asm("fma.rn.f32x2 %0,%1,%2,%3;" : "=l"(d) : "l"(a), "l"(b), "l"(c)); return d;
}
__device__ __forceinline__ u64 fmul2(u64 a, u64 b) {
    u64 d; asm("mul.rn.f32x2 %0,%1,%2;" : "=l"(d) : "l"(a), "l"(b)); return d;
}
__device__ __forceinline__ u64 pack2(float x, float y) {
    u64 d; asm("mov.b64 %0,{%1,%2};" : "=l"(d) : "f"(x), "f"(y)); return d;
}
__device__ __forceinline__ float2 unpack2(u64 a) {
    float x, y; asm("mov.b64 {%0,%1},%2;" : "=f"(x), "=f"(y) : "l"(a)); return make_float2(x, y);
}
__device__ __forceinline__ void pack_hl(float4 o, uint2& h, uint2& l) {
    bf162 h0 = __floats2bfloat162_rn(o.x, o.y);
    bf162 h1 = __floats2bfloat162_rn(o.z, o.w);
    h.x = *(uint32_t*)&h0;  h.y = *(uint32_t*)&h1;
    bf162 l0 = __floats2bfloat162_rn(o.x - __bfloat162float(h0.x), o.y - __bfloat162float(h0.y));
    bf162 l1 = __floats2bfloat162_rn(o.z - __bfloat162float(h1.x), o.w - __bfloat162float(h1.y));
    l.x = *(uint32_t*)&l0;  l.y = *(uint32_t*)&l1;
}

// ---- mbarrier / TMA ----
#define MBARRIER_INIT(addr, cnt) \
    asm volatile("mbarrier.init.shared.b64 [%0], %1;" :: "r"((uint32_t)(addr)), "r"((uint32_t)(cnt)) : "memory")
#define MBARRIER_EXPECT_TX(addr, bytes) \
    asm volatile("mbarrier.arrive.expect_tx.shared.b64 _, [%0], %1;" :: "r"((uint32_t)(addr)), "r"((uint32_t)(bytes)) : "memory")
#define TMA2D(dst, map, cx, cy, mbar) \
    asm volatile("cp.async.bulk.tensor.2d.shared::cta.global.tile.mbarrier::complete_tx::bytes [%0],[%1,{%2,%3}],[%4];" \
        :: "r"((uint32_t)(dst)), "l"(map), "r"((int)(cx)), "r"((int)(cy)), "r"((uint32_t)(mbar)) : "memory")

__device__ __forceinline__ void mbar_wait(uint32_t addr, int phase) {
    asm volatile(
        "{\n\t.reg .pred P1;\n\t"
        "WAIT_LOOP_%=:\n\t"
        "mbarrier.try_wait.parity.shared.b64 P1, [%0], %1, 0x989680;\n\t"
        "@P1 bra.uni WAIT_DONE_%=;\n\t"
        "bra.uni WAIT_LOOP_%=;\n\t"
        "WAIT_DONE_%=:\n\t}"
        :: "r"(addr), "r"((uint32_t)phase) : "memory");
}

// ---------------- transpose + split: W[K,N] fp32 -> pool[N,K] bf16 hi/lo ----------------
struct TJobs { const float* src[10]; int dstoff[10]; int K[10]; int N[10]; int tbase[11]; };

__global__ void tsplit_kernel(TJobs jb, bf16* __restrict__ hi, bf16* __restrict__ lo)
{
    __shared__ float s[32][33];
    int bid = blockIdx.x;
    int j = 0;
#pragma unroll
    for (int q = 1; q < 10; q++) if (bid >= jb.tbase[q]) j = q;
    int tl = bid - jb.tbase[j];
    int K = jb.K[j], N = jb.N[j];
    int ntn = N >> 5;
    int tn = tl % ntn, tk = tl / ntn;
    const float* src = jb.src[j];
    int tx = threadIdx.x, ty = threadIdx.y;   // 32 x 8
#pragma unroll
    for (int i = 0; i < 4; i++) {
        int r = tk*32 + ty + i*8, c = tn*32 + tx;
        s[ty + i*8][tx] = src[(size_t)r * N + c];
    }
    __syncthreads();
#pragma unroll
    for (int i = 0; i < 4; i++) {
        int n = tn*32 + ty + i*8, k = tk*32 + tx;
        float v = s[tx][ty + i*8];
        bf16 h = __float2bfloat16_rn(v);
        size_t di = (size_t)jb.dstoff[j] + (size_t)n * K + k;
        hi[di] = h;
        lo[di] = __float2bfloat16_rn(v - __bfloat162float(h));
    }
}

// ---------------- token shift + 6-way mix, emitting hi/lo bf16 ----------------
__global__ void mix_kernel(const float* __restrict__ x,
                           const float* __restrict__ mr, const float* __restrict__ mw,
                           const float* __restrict__ mk, const float* __restrict__ mv,
                           const float* __restrict__ ma, const float* __restrict__ mg,
                           bf16* __restrict__ xh, bf16* __restrict__ xl)
{
    int idx = blockIdx.x * blockDim.x + threadIdx.x;     // float4 index
    const int total = BTz * Cz / 4;
    if (idx >= total) return;
    int c4 = idx % (Cz / 4);
    int bt = idx / (Cz / 4);
    int t  = bt % Tz;
    const float4* x4 = (const float4*)x;
    float4 cur = x4[idx];
    float4 prev = make_float4(0.f, 0.f, 0.f, 0.f);
    if (t > 0) prev = x4[idx - Cz / 4];
    float4 xx = make_float4(prev.x - cur.x, prev.y - cur.y, prev.z - cur.z, prev.w - cur.w);
    int c = c4 * 4;
    const float* ms[6] = { mr, mw, mk, mv, ma, mg };
#pragma unroll
    for (int s = 0; s < 6; s++) {
        float4 mm = *(const float4*)(ms[s] + c);
        float4 o;
        o.x = cur.x + xx.x * mm.x;  o.y = cur.y + xx.y * mm.y;
        o.z = cur.z + xx.z * mm.z;  o.w = cur.w + xx.w * mm.w;
        uint2 h, l;
        pack_hl(o, h, l);
        ((uint2*)(xh + (size_t)s * BTz * Cz))[idx] = h;
        ((uint2*)(xl + (size_t)s * BTz * Cz))[idx] = l;
    }
}

// ---------------- epilogue ----------------
__device__ __forceinline__ float apply_epi_rt(float acc, float b, int epi)
{
    float pre = acc + b;
    if (epi == 0) return pre;
    if (epi == 1) return tanhf(pre);
    if (epi == 2) return 1.f / (1.f + expf(-pre));
    float sp = (pre > -30.f) ? log1pf(expf(-pre)) : -pre;   // softplus(-pre)
    return expf(-expf(-sp - 0.5f));
}

// ---------------- TMA + mma.sync GEMM: C = Ah*Bh + Ah*Bl + Al*Bh ----------------
// A [M,K] K-major tiles (SW128), B pre-transposed [N,K] K-major tiles (SW128).
// BM=128, BK=64 (exact 128-byte SW128 rows). 256 threads, 2-stage TMA pipeline.
template<int BN, int OUT>
__global__ __launch_bounds__(256, 1)
void tc_gemm(const __grid_constant__ CUtensorMap mAh,
             const __grid_constant__ CUtensorMap mAl,
             const __grid_constant__ CUtensorMap mBh,
             const __grid_constant__ CUtensorMap mBl,
             int K,
             float* __restrict__ C, bf16* __restrict__ Ch, bf16* __restrict__ Cl,
             int ldc, const float* __restrict__ bias, int epi)
{
    constexpr int BM = 128;
    constexpr int ATILE = BM*128;              // bytes per A plane (BMx64 bf16)
    constexpr int BTILE = BN*128;              // bytes per B plane
    constexpr int STAGE = 2*ATILE + 2*BTILE;
    constexpr int WM = (BN == 128) ? 64 : 32;
    constexpr int WN = 32;
    constexpr int MFR = WM/16, NFR = WN/8;

    extern __shared__ __align__(1024) char dsm[];
    uint32_t raw  = su32(dsm);
    uint32_t ctrl = (raw + 1023u) & ~1023u;
    uint32_t tiles = ctrl + 1024;              // ctrl+16/24: full mbarriers

    const int tid = threadIdx.x, lane = tid & 31, warp = tid >> 5;
    const int wN = warp % (BN/WN), wM = warp / (BN/WN);
    const int row0 = blockIdx.y * BM, col0 = blockIdx.x * BN;
    const int T = K >> 6;

    if (tid == 0) { MBARRIER_INIT(ctrl+16, 1); MBARRIER_INIT(ctrl+24, 1); }
    __syncthreads();

    float acc[MFR][NFR][4];
#pragma unroll
    for (int i = 0; i < MFR; i++)
#pragma unroll
        for (int j = 0; j < NFR; j++)
#pragma unroll
            for (int q = 0; q < 4; q++) acc[i][j][q] = 0.f;

    // per-lane swizzle constants: sw addr = rowbase + (colbytes ^ ((row&7)<<4))
    const uint32_t swm = (uint32_t)((lane & 7) << 4);
    uint32_t aRow[MFR], bRow[NFR/2];
#pragma unroll
    for (int fm = 0; fm < MFR; fm++)
        aRow[fm] = (uint32_t)((wM*WM + fm*16 + (lane & 15)) * 128);
#pragma unroll
    for (int p = 0; p < NFR/2; p++)
        bRow[p] = (uint32_t)((wN*WN + p*16 + (lane & 7) + ((lane >> 4) << 3)) * 128);
    const uint32_t aColB = (uint32_t)((lane >> 4) * 16);        // bytes
    const uint32_t bColB = (uint32_t)(((lane >> 3) & 1) * 16);  // bytes

    auto issue_stage = [&](int s, int k0) {
        uint32_t sb = tiles + s*STAGE;
        uint32_t fb = ctrl + 16 + 8*s;
        MBARRIER_EXPECT_TX(fb, (uint32_t)STAGE);
        TMA2D(sb,               &mAh, k0, row0, fb);
        TMA2D(sb+ATILE,         &mAl, k0, row0, fb);
        TMA2D(sb+2*ATILE,       &mBh, k0, col0, fb);
        TMA2D(sb+2*ATILE+BTILE, &mBl, k0, col0, fb);
    };

    if (tid == 0) {
        issue_stage(0, 0);
        if (T > 1) issue_stage(1, 64);
    }

    int ph[2] = {0, 0};
    for (int t = 0; t < T; t++) {
        const int s = t & 1;
        mbar_wait(ctrl + 16 + 8*s, ph[s]);
        ph[s] ^= 1;
        const uint32_t aH = tiles + s*STAGE;
        const uint32_t aL = aH + ATILE;
        const uint32_t bH = aH + 2*ATILE;
        const uint32_t bL = bH + BTILE;
#pragma unroll
        for (int kk = 0; kk < 4; kk++) {
            const uint32_t aC = (uint32_t)(kk*32) + aColB;
            const uint32_t bC = (uint32_t)(kk*32) + bColB;
            uint32_t Afh[MFR][4], Afl[MFR][4], Bfh[NFR][2], Bfl[NFR][2];
#pragma unroll
            for (int fm = 0; fm < MFR; fm++) {
                uint32_t off = aRow[fm] + (aC ^ swm);
                ldsm4(Afh[fm][0], Afh[fm][1], Afh[fm][2], Afh[fm][3], aH + off);
                ldsm4(Afl[fm][0], Afl[fm][1], Afl[fm][2], Afl[fm][3], aL + off);
            }
#pragma unroll
            for (int p = 0; p < NFR/2; p++) {
                uint32_t off = bRow[p] + (bC ^ swm);
                uint32_t t0, t1, t2, t3;
                ldsm4(t0, t1, t2, t3, bH + off);
                Bfh[2*p][0] = t0; Bfh[2*p][1] = t1; Bfh[2*p+1][0] = t2; Bfh[2*p+1][1] = t3;
                ldsm4(t0, t1, t2, t3, bL + off);
                Bfl[2*p][0] = t0; Bfl[2*p][1] = t1; Bfl[2*p+1][0] = t2; Bfl[2*p+1][1] = t3;
            }
#pragma unroll
            for (int fm = 0; fm < MFR; fm++)
#pragma unroll
                for (int fn = 0; fn < NFR; fn++) {
                    mma16816(acc[fm][fn], Afh[fm], Bfh[fn]);
                    mma16816(acc[fm][fn], Afh[fm], Bfl[fn]);
                    mma16816(acc[fm][fn], Afl[fm], Bfh[fn]);
                }
        }
        __syncthreads();
        if (tid == 0 && t + 2 < T) issue_stage(s, (t + 2) * 64);
    }

    // epilogue
#pragma unroll
    for (int fm = 0; fm < MFR; fm++) {
        int r = row0 + wM*WM + fm*16 + (lane >> 2);
#pragma unroll
        for (int fn = 0; fn < NFR; fn++) {
            int c = col0 + wN*WN + fn*8 + 2*(lane & 3);
            float b0 = bias ? bias[c] : 0.f;
            float b1 = bias ? bias[c+1] : 0.f;
            float x0 = apply_epi_rt(acc[fm][fn][0], b0, epi);
            float x1 = apply_epi_rt(acc[fm][fn][1], b1, epi);
            float x2 = apply_epi_rt(acc[fm][fn][2], b0, epi);
            float x3 = apply_epi_rt(acc[fm][fn][3], b1, epi);
            if (OUT == 0) {
                *(float2*)&C[(size_t)r*ldc + c]     = make_float2(x0, x1);
                *(float2*)&C[(size_t)(r+8)*ldc + c] = make_float2(x2, x3);
            } else {
                bf162 h0 = __floats2bfloat162_rn(x0, x1);
                bf162 h1 = __floats2bfloat162_rn(x2, x3);
                *(bf162*)&Ch[(size_t)r*ldc + c]     = h0;
                *(bf162*)&Ch[(size_t)(r+8)*ldc + c] = h1;
                bf162 l0 = __floats2bfloat162_rn(x0 - __bfloat162float(h0.x), x1 - __bfloat162float(h0.y));
                bf162 l1 = __floats2bfloat162_rn(x2 - __bfloat162float(h1.x), x3 - __bfloat162float(h1.y));
                *(bf162*)&Cl[(size_t)r*ldc + c]     = l0;
                *(bf162*)&Cl[(size_t)(r+8)*ldc + c] = l1;
            }
        }
    }
}

// ---------------- kk normalize, aa, bb, k update ----------------
__global__ void prep_kernel(const float* __restrict__ kkw, const float* __restrict__ kaw)
{
    int gw   = (blockIdx.x * blockDim.x + threadIdx.x) >> 5;
    int lane = threadIdx.x & 31;
    if (gw >= BTz * Hz) return;
    int bt = gw / Hz, h = gw % Hz;
    int c0 = h * 64 + lane, c1 = c0 + 32;
    size_t base = (size_t)bt * Cz;
    float k0 = g_k[base + c0], k1 = g_k[base + c1];
    float kk0 = k0 * kkw[c0], kk1 = k1 * kkw[c1];
    float ss = kk0*kk0 + kk1*kk1;
#pragma unroll
    for (int m = 16; m > 0; m >>= 1) ss += __shfl_xor_sync(0xffffffffu, ss, m);
    float inv = 1.f / fmaxf(sqrtf(ss), 1e-12f);
    float a0 = g_a[base + c0], a1v = g_a[base + c1];
    kk0 *= inv; kk1 *= inv;
    g_aa[base + c0] = -kk0;       g_aa[base + c1] = -kk1;
    g_bb[base + c0] = kk0 * a0;   g_bb[base + c1] = kk1 * a1v;
    g_k [base + c0] = k0 * (1.f + (a0  - 1.f) * kaw[c0]);
    g_k [base + c1] = k1 * (1.f + (a1v - 1.f) * kaw[c1]);
}

// ---------------- sequential RWKV7 state scan (f32x2 packed, 256 thr) ----------------
__global__ __launch_bounds__(256)
void scan_kernel(const float* __restrict__ r, const float* __restrict__ wdec,
                 const float* __restrict__ k, const float* __restrict__ aa,
                 const float* __restrict__ bb, const float* __restrict__ v,
                 float* __restrict__ o)
{
    const int bh = blockIdx.x;
    const int b = bh / Hz, h = bh % Hz;
    const int tid = threadIdx.x;
    const int i  = tid >> 2;
    const int jq = tid & 3;
    const int jb = jq * 16;

    __shared__ __align__(16) float sm[2][6*64];
    u64 S2[8];
#pragma unroll
    for (int q = 0; q < 8; q++) S2[q] = 0ULL;

    const size_t base = (size_t)b * Tz * Cz + h * 64;
    const float* vp[6] = { r + base, wdec + base, k + base, aa + base, bb + base, v + base };

    const float* myp[2]; int mys[2]; int nslot = (tid < 128) ? 2 : 1;
#pragma unroll
    for (int u = 0; u < 2; u++) {
        int lin = u * 256 + tid;
        if (lin >= 384) lin = 0;
        int vec = lin >> 6;
        int idx = lin & 63;
        const float* p = vp[0];
        if (vec == 1) p = vp[1]; else if (vec == 2) p = vp[2];
        else if (vec == 3) p = vp[3]; else if (vec == 4) p = vp[4];
        else if (vec == 5) p = vp[5];
        myp[u] = p + idx;
        mys[u] = lin;
    }

    for (int u = 0; u < nslot; u++) sm[0][mys[u]] = myp[u][0];
    __syncthreads();

    float* obase = o + base;
    for (int t = 0; t < Tz; t++) {
        const int cur = t & 1;
        if (t + 1 < Tz) {
            size_t off = (size_t)(t + 1) * Cz;
            for (int u = 0; u < nslot; u++) sm[cur ^ 1][mys[u]] = myp[u][off];
        }
        const float* s_r  = &sm[cur][0];
        const float* s_w  = &sm[cur][64];
        const float* s_k  = &sm[cur][128];
        const float* s_aa = &sm[cur][192];
        const float* s_bb = &sm[cur][256];
        const float* s_v  = &sm[cur][320];

        u64 p0 = 0ULL, p1 = 0ULL;
#pragma unroll
        for (int g = 0; g < 4; g++) {
            ulonglong2 a2 = *(const ulonglong2*)&s_aa[jb + 4*g];
            p0 = ffma2(S2[2*g],   a2.x, p0);
            p1 = ffma2(S2[2*g+1], a2.y, p1);
        }
        float2 f0 = unpack2(p0), f1 = unpack2(p1);
        float sa = (f0.x + f0.y) + (f1.x + f1.y);
        sa += __shfl_xor_sync(0xffffffffu, sa, 1);
        sa += __shfl_xor_sync(0xffffffffu, sa, 2);
        const u64 sa2 = pack2(sa, sa);
        const float vi = s_v[i];
        const u64 vi2 = pack2(vi, vi);

        u64 o0 = 0ULL, o1 = 0ULL;
#pragma unroll
        for (int g = 0; g < 4; g++) {
            ulonglong2 w2 = *(const ulonglong2*)&s_w [jb + 4*g];
            ulonglong2 b2 = *(const ulonglong2*)&s_bb[jb + 4*g];
            ulonglong2 k2 = *(const ulonglong2*)&s_k [jb + 4*g];
            ulonglong2 r2 = *(const ulonglong2*)&s_r [jb + 4*g];
            S2[2*g]   = ffma2(S2[2*g],   w2.x, ffma2(sa2, b2.x, fmul2(vi2, k2.x)));
            o0        = ffma2(S2[2*g],   r2.x, o0);
            S2[2*g+1] = ffma2(S2[2*g+1], w2.y, ffma2(sa2, b2.y, fmul2(vi2, k2.y)));
            o1        = ffma2(S2[2*g+1], r2.y, o1);
        }
        float2 q0 = unpack2(o0), q1 = unpack2(o1);
        float out = (q0.x + q0.y) + (q1.x + q1.y);
        out += __shfl_xor_sync(0xffffffffu, out, 1);
        out += __shfl_xor_sync(0xffffffffu, out, 2);
        if (jq == 0) obase[(size_t)t * Cz + i] = out;
        __syncthreads();
    }
}

// ---------------- groupnorm + rk bonus + gate -> hi/lo bf16 ----------------
__global__ void post_kernel(const float* __restrict__ rk,
                            const float* __restrict__ gamma, const float* __restrict__ beta)
{
    int gw   = (blockIdx.x * blockDim.x + threadIdx.x) >> 5;
    int lane = threadIdx.x & 31;
    if (gw >= BTz * Hz) return;
    int bt = gw / Hz, h = gw % Hz;
    int c0 = h * 64 + lane, c1 = c0 + 32;
    size_t base = (size_t)bt * Cz;
    float o0 = g_o[base + c0], o1 = g_o[base + c1];
    float s1 = o0 + o1;
    float s2 = o0*o0 + o1*o1;
    float r0 = g_r[base + c0], r1 = g_r[base + c1];
    float k0 = g_k[base + c0], k1 = g_k[base + c1];
    float bon = r0 * k0 * rk[h * 64 + lane] + r1 * k1 * rk[h * 64 + lane + 32];
#pragma unroll
    for (int m = 16; m > 0; m >>= 1) {
        s1  += __shfl_xor_sync(0xffffffffu, s1,  m);
        s2  += __shfl_xor_sync(0xffffffffu, s2,  m);
        bon += __shfl_xor_sync(0xffffffffu, bon, m);
    }
    float mu   = s1 * (1.f / 64.f);
    float var  = s2 * (1.f / 64.f) - mu * mu;
    float rstd = rsqrtf(var + 0.00064f);
    float v0 = g_v[base + c0], v1 = g_v[base + c1];
    float y0 = ((o0 - mu) * rstd * gamma[c0] + beta[c0] + bon * v0) * g_g[base + c0];
    float y1 = ((o1 - mu) * rstd * gamma[c1] + beta[c1] + bon * v1) * g_g[base + c1];
    bf16 h0 = __float2bfloat16_rn(y0);
    bf16 h1 = __float2bfloat16_rn(y1);
    g_ygh[base + c0] = h0;  g_ygh[base + c1] = h1;
    g_ygl[base + c0] = __float2bfloat16_rn(y0 - __bfloat162float(h0));
    g_ygl[base + c1] = __float2bfloat16_rn(y1 - __bfloat162float(h1));
}

// ---------------- host: tensormap builder ----------------
typedef CUresult (*PFN_encode)(CUtensorMap*, CUtensorMapDataType, cuuint32_t, void*,
                               const cuuint64_t*, const cuuint64_t*, const cuuint32_t*,
                               const cuuint32_t*, CUtensorMapInterleave, CUtensorMapSwizzle,
                               CUtensorMapL2promotion, CUtensorMapFloatOOBfill);

static void make_map(PFN_encode enc, CUtensorMap* m, const void* base,
                     unsigned long long d0, unsigned long long d1,
                     unsigned long long stride1B, unsigned box0, unsigned box1)
{
    cuuint64_t dims[2]    = { d0, d1 };
    cuuint64_t strides[1] = { stride1B };
    cuuint32_t box[2]     = { box0, box1 };
    cuuint32_t es[2]      = { 1, 1 };
    enc(m, CU_TENSOR_MAP_DATA_TYPE_BFLOAT16, 2, (void*)base, dims, strides, box, es,
        CU_TENSOR_MAP_INTERLEAVE_NONE, CU_TENSOR_MAP_SWIZZLE_128B,
        CU_TENSOR_MAP_L2_PROMOTION_L2_128B, CU_TENSOR_MAP_FLOAT_OOB_FILL_NONE);
}

#define SMEM_128 (1024 + 1024 + 2*(2*128*128 + 2*128*128))
#define SMEM_64  (1024 + 1024 + 2*(2*128*128 + 2*64*128))

// ---------------- launch ----------------
extern "C" void kernel_launch(void* const* d_in, const int* in_sizes, int n_in,
                              void* d_out, int out_size)
{
    const float* x    = (const float*)d_in[0];
    const float* x_r  = (const float*)d_in[1];
    const float* x_w  = (const float*)d_in[2];
    const float* x_k  = (const float*)d_in[3];
    const float* x_v  = (const float*)d_in[4];
    const float* x_a  = (const float*)d_in[5];
    const float* x_g  = (const float*)d_in[6];
    const float* w0   = (const float*)d_in[7];
    const float* w1   = (const float*)d_in[8];
    const float* w2   = (const float*)d_in[9];
    const float* a0   = (const float*)d_in[10];
    const float* a1   = (const float*)d_in[11];
    const float* a2   = (const float*)d_in[12];
    const float* g1   = (const float*)d_in[16];
    const float* g2   = (const float*)d_in[17];
    const float* k_k  = (const float*)d_in[18];
    const float* k_a  = (const float*)d_in[19];
    const float* r_k  = (const float*)d_in[20];
    const float* Wr   = (const float*)d_in[21];
    const float* Wk   = (const float*)d_in[22];
    const float* Wv   = (const float*)d_in[23];
    const float* Wo   = (const float*)d_in[24];
    const float* lg   = (const float*)d_in[25];
    const float* lb   = (const float*)d_in[26];

    void *pr, *pk, *pv, *pwd, *pa, *pg, *paa, *pbb, *po;
    void *pxh, *pxl, *pygh, *pygl, *phh, *phl, *pwh, *pwl;
    cudaGetSymbolAddress(&pr,  g_r);   cudaGetSymbolAddress(&pk,  g_k);
    cudaGetSymbolAddress(&pv,  g_v);   cudaGetSymbolAddress(&pwd, g_wd);
    cudaGetSymbolAddress(&pa,  g_a);   cudaGetSymbolAddress(&pg,  g_g);
    cudaGetSymbolAddress(&paa, g_aa);  cudaGetSymbolAddress(&pbb, g_bb);
    cudaGetSymbolAddress(&po,  g_o);
    cudaGetSymbolAddress(&pxh, g_xh);  cudaGetSymbolAddress(&pxl, g_xl);
    cudaGetSymbolAddress(&pygh, g_ygh); cudaGetSymbolAddress(&pygl, g_ygl);
    cudaGetSymbolAddress(&phh, g_hh);  cudaGetSymbolAddress(&phl, g_hl);
    cudaGetSymbolAddress(&pwh, g_wh);  cudaGetSymbolAddress(&pwl, g_wl);

    float *rb = (float*)pr, *kb = (float*)pk, *vb = (float*)pv, *wd = (float*)pwd;
    float *ab = (float*)pa, *gb = (float*)pg, *aab = (float*)paa, *bbb = (float*)pbb;
    float *ob = (float*)po;
    bf16 *xh = (bf16*)pxh, *xl = (bf16*)pxl;
    bf16 *ygh = (bf16*)pygh, *ygl = (bf16*)pygl;
    bf16 *hh = (bf16*)phh, *hl = (bf16*)phl;
    bf16 *wh = (bf16*)pwh, *wl = (bf16*)pwl;

    const size_t S = (size_t)BTz * Cz;

    cudaFuncSetAttribute(tc_gemm<128,0>, cudaFuncAttributeMaxDynamicSharedMemorySize, SMEM_128);
    cudaFuncSetAttribute(tc_gemm<64,1>,  cudaFuncAttributeMaxDynamicSharedMemorySize, SMEM_64);

    PFN_encode enc = nullptr;
    cudaDriverEntryPointQueryResult qres;
    cudaGetDriverEntryPoint("cuTensorMapEncodeTiled", (void**)&enc,
                            cudaEnableDefault, &qres);

    // 1. transpose+split all weights into the pool
    TJobs jb;
    jb.src[0]=Wr; jb.src[1]=Wk; jb.src[2]=Wv; jb.src[3]=Wo;
    jb.src[4]=w1; jb.src[5]=a1; jb.src[6]=g1;
    jb.src[7]=w2; jb.src[8]=a2; jb.src[9]=g2;
    jb.dstoff[0]=O_Wr; jb.dstoff[1]=O_Wk; jb.dstoff[2]=O_Wv; jb.dstoff[3]=O_Wo;
    jb.dstoff[4]=O_L1; jb.dstoff[5]=O_L1+64*Cz; jb.dstoff[6]=O_L1+128*Cz;
    jb.dstoff[7]=O_W2T; jb.dstoff[8]=O_A2T; jb.dstoff[9]=O_G2T;
    jb.K[0]=jb.K[1]=jb.K[2]=jb.K[3]=Cz; jb.K[4]=jb.K[5]=jb.K[6]=Cz;
    jb.K[7]=64; jb.K[8]=64; jb.K[9]=128;
    jb.N[0]=jb.N[1]=jb.N[2]=jb.N[3]=Cz; jb.N[4]=64; jb.N[5]=64; jb.N[6]=128;
    jb.N[7]=Cz; jb.N[8]=Cz; jb.N[9]=Cz;
    int tb = 0;
    for (int j = 0; j < 10; j++) { jb.tbase[j] = tb; tb += (jb.K[j]/32)*(jb.N[j]/32); }
    jb.tbase[10] = tb;
    tsplit_kernel<<<tb, dim3(32,8)>>>(jb, wh, wl);

    // 2. token shift + mix
    mix_kernel<<<(BTz*Cz/4 + 255)/256, 256>>>(x, x_r, x_w, x_k, x_v, x_a, x_g, xh, xl);

    CUtensorMap mAh, mAl, mBh, mBl;
    dim3 bg(Cz/128, BTz/128);

    // 3-5. LoRA stage-1 (BN=64, OUT=1 -> hidden pool hi/lo)
    {   // hw = tanh(xw@w1) -> hidden cols 0-63
        make_map(enc, &mAh, xh + 1*S, Cz, BTz, Cz*2, 64, 128);
        make_map(enc, &mAl, xl + 1*S, Cz, BTz, Cz*2, 64, 128);
        make_map(enc, &mBh, wh + O_L1, Cz, 64, Cz*2, 64, 64);
        make_map(enc, &mBl, wl + O_L1, Cz, 64, Cz*2, 64, 64);
        tc_gemm<64,1><<<dim3(1, BTz/128), 256, SMEM_64>>>(mAh, mAl, mBh, mBl, Cz,
            nullptr, hh, hl, 256, nullptr, 1);
    }
    {   // ha = xa@a1 -> hidden cols 64-127
        make_map(enc, &mAh, xh + 4*S, Cz, BTz, Cz*2, 64, 128);
        make_map(enc, &mAl, xl + 4*S, Cz, BTz, Cz*2, 64, 128);
        make_map(enc, &mBh, wh + O_L1 + 64*Cz, Cz, 64, Cz*2, 64, 64);
        make_map(enc, &mBl, wl + O_L1 + 64*Cz, Cz, 64, Cz*2, 64, 64);
        tc_gemm<64,1><<<dim3(1, BTz/128), 256, SMEM_64>>>(mAh, mAl, mBh, mBl, Cz,
            nullptr, hh + 64, hl + 64, 256, nullptr, 0);
    }
    {   // hg = sigmoid(xg@g1) -> hidden cols 128-255
        make_map(enc, &mAh, xh + 5*S, Cz, BTz, Cz*2, 64, 128);
        make_map(enc, &mAl, xl + 5*S, Cz, BTz, Cz*2, 64, 128);
        make_map(enc, &mBh, wh + O_L1 + 128*Cz, Cz, 128, Cz*2, 64, 64);
        make_map(enc, &mBl, wl + O_L1 + 128*Cz, Cz, 128, Cz*2, 64, 64);
        tc_gemm<64,1><<<dim3(2, BTz/128), 256, SMEM_64>>>(mAh, mAl, mBh, mBl, Cz,
            nullptr, hh + 128, hl + 128, 256, nullptr, 2);
    }

    // 6-8. big projections r, k, v (launch 6 = R projection, profiled)
    {
        make_map(enc, &mAh, xh + 0*S, Cz, BTz, Cz*2, 64, 128);
        make_map(enc, &mAl, xl + 0*S, Cz, BTz, Cz*2, 64, 128);
        make_map(enc, &mBh, wh + O_Wr, Cz, Cz, Cz*2, 64, 128);
        make_map(enc, &mBl, wl + O_Wr, Cz, Cz, Cz*2, 64, 128);
        tc_gemm<128,0><<<bg, 256, SMEM_128>>>(mAh, mAl, mBh, mBl, Cz,
            rb, nullptr, nullptr, Cz, nullptr, 0);
    }
    {
        make_map(enc, &mAh, xh + 2*S, Cz, BTz, Cz*2, 64, 128);
        make_map(enc, &mAl, xl + 2*S, Cz, BTz, Cz*2, 64, 128);
        make_map(enc, &mBh, wh + O_Wk, Cz, Cz, Cz*2, 64, 128);
        make_map(enc, &mBl, wl + O_Wk, Cz, Cz, Cz*2, 64, 128);
        tc_gemm<128,0><<<bg, 256, SMEM_128>>>(mAh, mAl, mBh, mBl, Cz,
            kb, nullptr, nullptr, Cz, nullptr, 0);
    }
    {
        make_map(enc, &mAh, xh + 3*S, Cz, BTz, Cz*2, 64, 128);
        make_map(enc, &mAl, xl + 3*S, Cz, BTz, Cz*2, 64, 128);
        make_map(enc, &mBh, wh + O_Wv, Cz, Cz, Cz*2, 64, 128);
        make_map(enc, &mBl, wl + O_Wv, Cz, Cz, Cz*2, 64, 128);
        tc_gemm<128,0><<<bg, 256, SMEM_128>>>(mAh, mAl, mBh, mBl, Cz,
            vb, nullptr, nullptr, Cz, nullptr, 0);
    }

    // 9-11. LoRA stage-2
    {   // wd = decay(w0 + hw @ w2)
        make_map(enc, &mAh, hh, 64, BTz, 256*2, 64, 128);
        make_map(enc, &mAl, hl, 64, BTz, 256*2, 64, 128);
        make_map(enc, &mBh, wh + O_W2T, 64, Cz, 64*2, 64, 128);
        make_map(enc, &mBl, wl + O_W2T, 64, Cz, 64*2, 64, 128);
        tc_gemm<128,0><<<bg, 256, SMEM_128>>>(mAh, mAl, mBh, mBl, 64,
            wd, nullptr, nullptr, Cz, w0, 3);
    }
    {   // a = sigmoid(a0 + ha @ a2)
        make_map(enc, &mAh, hh + 64, 64, BTz, 256*2, 64, 128);
        make_map(enc, &mAl, hl + 64, 64, BTz, 256*2, 64, 128);
        make_map(enc, &mBh, wh + O_A2T, 64, Cz, 64*2, 64, 128);
        make_map(enc, &mBl, wl + O_A2T, 64, Cz, 64*2, 64, 128);
        tc_gemm<128,0><<<bg, 256, SMEM_128>>>(mAh, mAl, mBh, mBl, 64,
            ab, nullptr, nullptr, Cz, a0, 2);
    }
    {   // g = hg @ g2
        make_map(enc, &mAh, hh + 128, 128, BTz, 256*2, 64, 128);
        make_map(enc, &mAl, hl + 128, 128, BTz, 256*2, 64, 128);
        make_map(enc, &mBh, wh + O_G2T, 128, Cz, 128*2, 64, 128);
        make_map(enc, &mBl, wl + O_G2T, 128, Cz, 128*2, 64, 128);
        tc_gemm<128,0><<<bg, 256, SMEM_128>>>(mAh, mAl, mBh, mBl, 128,
            gb, nullptr, nullptr, Cz, nullptr, 0);
    }

    // 12. kk normalize / aa / bb / k update
    prep_kernel<<<BTz*Hz/8, 256>>>(k_k, k_a);

    // 13. sequential scan
    scan_kernel<<<Bz*Hz, 256>>>(rb, wd, kb, aab, bbb, vb, ob);

    // 14. groupnorm + bonus + gate
    post_kernel<<<BTz*Hz/8, 256>>>(r_k, lg, lb);

    // 15. output projection
    {
        make_map(enc, &mAh, ygh, Cz, BTz, Cz*2, 64, 128);
        make_map(enc, &mAl, ygl, Cz, BTz, Cz*2, 64, 128);
        make_map(enc, &mBh, wh + O_Wo, Cz, Cz, Cz*2, 64, 128);
        make_map(enc, &mBl, wl + O_Wo, Cz, Cz, Cz*2, 64, 128);
        tc_gemm<128,0><<<bg, 256, SMEM_128>>>(mAh, mAl, mBh, mBl, Cz,
            (float*)d_out, nullptr, nullptr, Cz, nullptr, 0);
    }

    // 16. v_first if expected
    if (out_size >= 2 * BTz * Cz) {
        cudaMemcpyAsync((float*)d_out + S, vb, sizeof(float) * S, cudaMemcpyDeviceToDevice);
    }
}

// round 9
// speedup vs baseline: 1.6828x; 1.1011x over previous
#include <cuda_runtime.h>
#include <cuda.h>
#include <cuda_bf16.h>
#include <cuda_fp16.h>
#include <cstdint>
#include <math.h>

#define Bz   4
#define Tz   1024
#define Cz   1024
#define Hz   16
#define BTz  (Bz*Tz)

typedef __half  f16;
typedef __half2 f162;
typedef unsigned long long u64;

// ---------------- scratch (device globals; no allocation allowed) ----------------
__device__ float g_r [BTz*Cz], g_k [BTz*Cz], g_v [BTz*Cz], g_wd[BTz*Cz];
__device__ float g_a [BTz*Cz], g_g [BTz*Cz], g_aa[BTz*Cz], g_bb[BTz*Cz], g_o [BTz*Cz];

__device__ __align__(256) f16 g_x6[6*BTz*Cz];     // mixed streams, single fp16 plane
__device__ __align__(256) f16 g_yg[BTz*Cz];       // (gn(o)+bonus)*g fp16
// LoRA hidden pool [BTz, 256]: cols 0-63 decay, 64-127 a, 128-255 g (fp16)
__device__ __align__(256) f16 g_hid[BTz*256];

// weight pool: all matrices stored TRANSPOSED [N, K] row-major, fp16 hi/lo
#define O_Wr 0
#define O_Wk (Cz*Cz)
#define O_Wv (2*Cz*Cz)
#define O_Wo (3*Cz*Cz)
#define O_L1 (4*Cz*Cz)                  // [256, 1024]: w1t 0-63, a1t 64-127, g1t 128-255
#define O_W2T (O_L1 + 256*Cz)           // [1024, 64]
#define O_A2T (O_W2T + Cz*64)           // [1024, 64]
#define O_G2T (O_A2T + Cz*64)           // [1024, 128]
#define WPOOL (O_G2T + Cz*128)
__device__ __align__(256) f16 g_wh[WPOOL], g_wl[WPOOL];

// ---------------- helpers ----------------
__device__ __forceinline__ uint32_t su32(const void* p) {
    return (uint32_t)__cvta_generic_to_shared(p);
}
__device__ __forceinline__ void ldsm4(uint32_t& a0, uint32_t& a1, uint32_t& a2, uint32_t& a3, uint32_t addr) {
    asm volatile("ldmatrix.sync.aligned.m8n8.x4.shared.b16 {%0,%1,%2,%3},[%4];"
                 : "=r"(a0), "=r"(a1), "=r"(a2), "=r"(a3) : "r"(addr));
}
__device__ __forceinline__ void mma16816(float* c, const uint32_t* a, const uint32_t* b) {
    asm volatile("mma.sync.aligned.m16n8k16.row.col.f32.f16.f16.f32 "
                 "{%0,%1,%2,%3},{%4,%5,%6,%7},{%8,%9},{%0,%1,%2,%3};"
                 : "+f"(c[0]), "+f"(c[1]), "+f"(c[2]), "+f"(c[3])
                 : "r"(a[0]), "r"(a[1]), "r"(a[2]), "r"(a[3]), "r"(b[0]), "r"(b[1]));
}
__device__ __forceinline__ u64 ffma2(u64 a, u64 b, u64 c) {
    u64 d; asm("fma.rn.f32x2 %0,%1,%2,%3;" : "=l"(d) : "l"(a), "l"(b), "l"(c)); return d;
}
__device__ __forceinline__ u64 fmul2(u64 a, u64 b) {
    u64 d; asm("mul.rn.f32x2 %0,%1,%2;" : "=l"(d) : "l"(a), "l"(b)); return d;
}
__device__ __forceinline__ u64 pack2(float x, float y) {
    u64 d; asm("mov.b64 %0,{%1,%2};" : "=l"(d) : "f"(x), "f"(y)); return d;
}
__device__ __forceinline__ float2 unpack2(u64 a) {
    float x, y; asm("mov.b64 {%0,%1},%2;" : "=f"(x), "=f"(y) : "l"(a)); return make_float2(x, y);
}

// ---- mbarrier / TMA ----
#define MBARRIER_INIT(addr, cnt) \
    asm volatile("mbarrier.init.shared.b64 [%0], %1;" :: "r"((uint32_t)(addr)), "r"((uint32_t)(cnt)) : "memory")
#define MBARRIER_EXPECT_TX(addr, bytes) \
    asm volatile("mbarrier.arrive.expect_tx.shared.b64 _, [%0], %1;" :: "r"((uint32_t)(addr)), "r"((uint32_t)(bytes)) : "memory")
#define TMA2D(dst, map, cx, cy, mbar) \
    asm volatile("cp.async.bulk.tensor.2d.shared::cta.global.tile.mbarrier::complete_tx::bytes [%0],[%1,{%2,%3}],[%4];" \
        :: "r"((uint32_t)(dst)), "l"(map), "r"((int)(cx)), "r"((int)(cy)), "r"((uint32_t)(mbar)) : "memory")

__device__ __forceinline__ void mbar_wait(uint32_t addr, int phase) {
    asm volatile(
        "{\n\t.reg .pred P1;\n\t"
        "WAIT_LOOP_%=:\n\t"
        "mbarrier.try_wait.parity.shared.b64 P1, [%0], %1, 0x989680;\n\t"
        "@P1 bra.uni WAIT_DONE_%=;\n\t"
        "bra.uni WAIT_LOOP_%=;\n\t"
        "WAIT_DONE_%=:\n\t}"
        :: "r"(addr), "r"((uint32_t)phase) : "memory");
}

// ---------------- transpose + split: W[K,N] fp32 -> pool[N,K] fp16 hi/lo ----------------
struct TJobs { const float* src[10]; int dstoff[10]; int K[10]; int N[10]; int tbase[11]; };

__global__ void tsplit_kernel(TJobs jb, f16* __restrict__ hi, f16* __restrict__ lo)
{
    __shared__ float s[32][33];
    int bid = blockIdx.x;
    int j = 0;
#pragma unroll
    for (int q = 1; q < 10; q++) if (bid >= jb.tbase[q]) j = q;
    int tl = bid - jb.tbase[j];
    int K = jb.K[j], N = jb.N[j];
    int ntn = N >> 5;
    int tn = tl % ntn, tk = tl / ntn;
    const float* src = jb.src[j];
    int tx = threadIdx.x, ty = threadIdx.y;   // 32 x 8
#pragma unroll
    for (int i = 0; i < 4; i++) {
        int r = tk*32 + ty + i*8, c = tn*32 + tx;
        s[ty + i*8][tx] = src[(size_t)r * N + c];
    }
    __syncthreads();
#pragma unroll
    for (int i = 0; i < 4; i++) {
        int n = tn*32 + ty + i*8, k = tk*32 + tx;
        float v = s[tx][ty + i*8];
        f16 h = __float2half_rn(v);
        size_t di = (size_t)jb.dstoff[j] + (size_t)n * K + k;
        hi[di] = h;
        lo[di] = __float2half_rn(v - __half2float(h));
    }
}

// ---------------- token shift + 6-way mix, emitting fp16 ----------------
__global__ void mix_kernel(const float* __restrict__ x,
                           const float* __restrict__ mr, const float* __restrict__ mw,
                           const float* __restrict__ mk, const float* __restrict__ mv,
                           const float* __restrict__ ma, const float* __restrict__ mg,
                           f16* __restrict__ xo)
{
    int idx = blockIdx.x * blockDim.x + threadIdx.x;     // float4 index
    const int total = BTz * Cz / 4;
    if (idx >= total) return;
    int c4 = idx % (Cz / 4);
    int bt = idx / (Cz / 4);
    int t  = bt % Tz;
    const float4* x4 = (const float4*)x;
    float4 cur = x4[idx];
    float4 prev = make_float4(0.f, 0.f, 0.f, 0.f);
    if (t > 0) prev = x4[idx - Cz / 4];
    float4 xx = make_float4(prev.x - cur.x, prev.y - cur.y, prev.z - cur.z, prev.w - cur.w);
    int c = c4 * 4;
    const float* ms[6] = { mr, mw, mk, mv, ma, mg };
#pragma unroll
    for (int s = 0; s < 6; s++) {
        float4 mm = *(const float4*)(ms[s] + c);
        f162 h0 = __floats2half2_rn(cur.x + xx.x * mm.x, cur.y + xx.y * mm.y);
        f162 h1 = __floats2half2_rn(cur.z + xx.z * mm.z, cur.w + xx.w * mm.w);
        uint2 h; h.x = *(uint32_t*)&h0; h.y = *(uint32_t*)&h1;
        ((uint2*)(xo + (size_t)s * BTz * Cz))[idx] = h;
    }
}

// ---------------- epilogue ----------------
__device__ __forceinline__ float apply_epi_rt(float acc, float b, int epi)
{
    float pre = acc + b;
    if (epi == 0) return pre;
    if (epi == 1) return tanhf(pre);
    if (epi == 2) return 1.f / (1.f + expf(-pre));
    float sp = (pre > -30.f) ? log1pf(expf(-pre)) : -pre;   // softplus(-pre)
    return expf(-expf(-sp - 0.5f));
}

// ---------------- TMA + mma.sync GEMM: C = A*Bh + A*Bl (fp16x2, fp32 acc) ----------------
// A [M,K] K-major fp16 tiles (SW128), B pre-transposed [N,K] fp16 hi/lo tiles (SW128).
// BM=128, BK=64 (exact 128-byte SW128 rows). 256 threads, 4-stage TMA pipeline.
template<int BN, int OUT>
__global__ __launch_bounds__(256, 1)
void tc_gemm(const __grid_constant__ CUtensorMap mA,
             const __grid_constant__ CUtensorMap mBh,
             const __grid_constant__ CUtensorMap mBl,
             int K,
             float* __restrict__ C, f16* __restrict__ Ch,
             int ldc, const float* __restrict__ bias, int epi)
{
    constexpr int BM = 128;
    constexpr int ATILE = BM*128;              // bytes: BMx64 fp16
    constexpr int BTILE = BN*128;              // bytes per B plane
    constexpr int STAGE = ATILE + 2*BTILE;
    constexpr int NSTG = 4;
    constexpr int WM = (BN == 128) ? 64 : 32;
    constexpr int WN = 32;
    constexpr int MFR = WM/16, NFR = WN/8;

    extern __shared__ __align__(1024) char dsm[];
    uint32_t raw  = su32(dsm);
    uint32_t ctrl = (raw + 1023u) & ~1023u;
    uint32_t tiles = ctrl + 1024;

    const int tid = threadIdx.x, lane = tid & 31, warp = tid >> 5;
    const int wN = warp % (BN/WN), wM = warp / (BN/WN);
    const int row0 = blockIdx.y * BM, col0 = blockIdx.x * BN;
    const int T = K >> 6;

    if (tid == 0) {
#pragma unroll
        for (int s = 0; s < NSTG; s++) MBARRIER_INIT(ctrl + 16 + 8*s, 1);
    }
    __syncthreads();

    float acc[MFR][NFR][4];
#pragma unroll
    for (int i = 0; i < MFR; i++)
#pragma unroll
        for (int j = 0; j < NFR; j++)
#pragma unroll
            for (int q = 0; q < 4; q++) acc[i][j][q] = 0.f;

    // per-lane swizzle constants: sw addr = rowbase + (colbytes ^ ((row&7)<<4))
    const uint32_t swm = (uint32_t)((lane & 7) << 4);
    uint32_t aRow[MFR], bRow[NFR/2];
#pragma unroll
    for (int fm = 0; fm < MFR; fm++)
        aRow[fm] = (uint32_t)((wM*WM + fm*16 + (lane & 15)) * 128);
#pragma unroll
    for (int p = 0; p < NFR/2; p++)
        bRow[p] = (uint32_t)((wN*WN + p*16 + (lane & 7) + ((lane >> 4) << 3)) * 128);
    const uint32_t aColB = (uint32_t)((lane >> 4) * 16);        // bytes
    const uint32_t bColB = (uint32_t)(((lane >> 3) & 1) * 16);  // bytes

    auto issue_stage = [&](int s, int k0) {
        uint32_t sb = tiles + s*STAGE;
        uint32_t fb = ctrl + 16 + 8*s;
        MBARRIER_EXPECT_TX(fb, (uint32_t)STAGE);
        TMA2D(sb,             &mA,  k0, row0, fb);
        TMA2D(sb+ATILE,       &mBh, k0, col0, fb);
        TMA2D(sb+ATILE+BTILE, &mBl, k0, col0, fb);
    };

    if (tid == 0) {
        const int npre = (T < NSTG) ? T : NSTG;
        for (int s = 0; s < npre; s++) issue_stage(s, s*64);
    }

    int ph[NSTG];
#pragma unroll
    for (int s = 0; s < NSTG; s++) ph[s] = 0;

    for (int t = 0; t < T; t++) {
        const int s = t & (NSTG-1);
        mbar_wait(ctrl + 16 + 8*s, ph[s]);
        ph[s] ^= 1;
        const uint32_t aB = tiles + s*STAGE;
        const uint32_t bH = aB + ATILE;
        const uint32_t bL = bH + BTILE;
#pragma unroll
        for (int kk = 0; kk < 4; kk++) {
            const uint32_t aC = (uint32_t)(kk*32) + aColB;
            const uint32_t bC = (uint32_t)(kk*32) + bColB;
            uint32_t Af[MFR][4], Bfh[NFR][2], Bfl[NFR][2];
#pragma unroll
            for (int fm = 0; fm < MFR; fm++) {
                uint32_t off = aRow[fm] + (aC ^ swm);
                ldsm4(Af[fm][0], Af[fm][1], Af[fm][2], Af[fm][3], aB + off);
            }
#pragma unroll
            for (int p = 0; p < NFR/2; p++) {
                uint32_t off = bRow[p] + (bC ^ swm);
                uint32_t t0, t1, t2, t3;
                ldsm4(t0, t1, t2, t3, bH + off);
                Bfh[2*p][0] = t0; Bfh[2*p][1] = t1; Bfh[2*p+1][0] = t2; Bfh[2*p+1][1] = t3;
                ldsm4(t0, t1, t2, t3, bL + off);
                Bfl[2*p][0] = t0; Bfl[2*p][1] = t1; Bfl[2*p+1][0] = t2; Bfl[2*p+1][1] = t3;
            }
#pragma unroll
            for (int fm = 0; fm < MFR; fm++)
#pragma unroll
                for (int fn = 0; fn < NFR; fn++) {
                    mma16816(acc[fm][fn], Af[fm], Bfh[fn]);
                    mma16816(acc[fm][fn], Af[fm], Bfl[fn]);
                }
        }
        __syncthreads();
        if (tid == 0 && t + NSTG < T) issue_stage(s, (t + NSTG) * 64);
    }

    // epilogue
#pragma unroll
    for (int fm = 0; fm < MFR; fm++) {
        int r = row0 + wM*WM + fm*16 + (lane >> 2);
#pragma unroll
        for (int fn = 0; fn < NFR; fn++) {
            int c = col0 + wN*WN + fn*8 + 2*(lane & 3);
            float b0 = bias ? bias[c] : 0.f;
            float b1 = bias ? bias[c+1] : 0.f;
            float x0 = apply_epi_rt(acc[fm][fn][0], b0, epi);
            float x1 = apply_epi_rt(acc[fm][fn][1], b1, epi);
            float x2 = apply_epi_rt(acc[fm][fn][2], b0, epi);
            float x3 = apply_epi_rt(acc[fm][fn][3], b1, epi);
            if (OUT == 0) {
                *(float2*)&C[(size_t)r*ldc + c]     = make_float2(x0, x1);
                *(float2*)&C[(size_t)(r+8)*ldc + c] = make_float2(x2, x3);
            } else {
                f162 h0 = __floats2half2_rn(x0, x1);
                f162 h1 = __floats2half2_rn(x2, x3);
                *(f162*)&Ch[(size_t)r*ldc + c]     = h0;
                *(f162*)&Ch[(size_t)(r+8)*ldc + c] = h1;
            }
        }
    }
}

// ---------------- kk normalize, aa, bb, k update ----------------
__global__ void prep_kernel(const float* __restrict__ kkw, const float* __restrict__ kaw)
{
    int gw   = (blockIdx.x * blockDim.x + threadIdx.x) >> 5;
    int lane = threadIdx.x & 31;
    if (gw >= BTz * Hz) return;
    int bt = gw / Hz, h = gw % Hz;
    int c0 = h * 64 + lane, c1 = c0 + 32;
    size_t base = (size_t)bt * Cz;
    float k0 = g_k[base + c0], k1 = g_k[base + c1];
    float kk0 = k0 * kkw[c0], kk1 = k1 * kkw[c1];
    float ss = kk0*kk0 + kk1*kk1;
#pragma unroll
    for (int m = 16; m > 0; m >>= 1) ss += __shfl_xor_sync(0xffffffffu, ss, m);
    float inv = 1.f / fmaxf(sqrtf(ss), 1e-12f);
    float a0 = g_a[base + c0], a1v = g_a[base + c1];
    kk0 *= inv; kk1 *= inv;
    g_aa[base + c0] = -kk0;       g_aa[base + c1] = -kk1;
    g_bb[base + c0] = kk0 * a0;   g_bb[base + c1] = kk1 * a1v;
    g_k [base + c0] = k0 * (1.f + (a0  - 1.f) * kaw[c0]);
    g_k [base + c1] = k1 * (1.f + (a1v - 1.f) * kaw[c1]);
}

// ---------------- sequential RWKV7 state scan (f32x2 packed, 256 thr) ----------------
__global__ __launch_bounds__(256)
void scan_kernel(const float* __restrict__ r, const float* __restrict__ wdec,
                 const float* __restrict__ k, const float* __restrict__ aa,
                 const float* __restrict__ bb, const float* __restrict__ v,
                 float* __restrict__ o)
{
    const int bh = blockIdx.x;
    const int b = bh / Hz, h = bh % Hz;
    const int tid = threadIdx.x;
    const int i  = tid >> 2;
    const int jq = tid & 3;
    const int jb = jq * 16;

    __shared__ __align__(16) float sm[2][6*64];
    u64 S2[8];
#pragma unroll
    for (int q = 0; q < 8; q++) S2[q] = 0ULL;

    const size_t base = (size_t)b * Tz * Cz + h * 64;
    const float* vp[6] = { r + base, wdec + base, k + base, aa + base, bb + base, v + base };

    const float* myp[2]; int mys[2]; int nslot = (tid < 128) ? 2 : 1;
#pragma unroll
    for (int u = 0; u < 2; u++) {
        int lin = u * 256 + tid;
        if (lin >= 384) lin = 0;
        int vec = lin >> 6;
        int idx = lin & 63;
        const float* p = vp[0];
        if (vec == 1) p = vp[1]; else if (vec == 2) p = vp[2];
        else if (vec == 3) p = vp[3]; else if (vec == 4) p = vp[4];
        else if (vec == 5) p = vp[5];
        myp[u] = p + idx;
        mys[u] = lin;
    }

    for (int u = 0; u < nslot; u++) sm[0][mys[u]] = myp[u][0];
    __syncthreads();

    float* obase = o + base;
    for (int t = 0; t < Tz; t++) {
        const int cur = t & 1;
        if (t + 1 < Tz) {
            size_t off = (size_t)(t + 1) * Cz;
            for (int u = 0; u < nslot; u++) sm[cur ^ 1][mys[u]] = myp[u][off];
        }
        const float* s_r  = &sm[cur][0];
        const float* s_w  = &sm[cur][64];
        const float* s_k  = &sm[cur][128];
        const float* s_aa = &sm[cur][192];
        const float* s_bb = &sm[cur][256];
        const float* s_v  = &sm[cur][320];

        u64 p0 = 0ULL, p1 = 0ULL;
#pragma unroll
        for (int g = 0; g < 4; g++) {
            ulonglong2 a2 = *(const ulonglong2*)&s_aa[jb + 4*g];
            p0 = ffma2(S2[2*g],   a2.x, p0);
            p1 = ffma2(S2[2*g+1], a2.y, p1);
        }
        float2 f0 = unpack2(p0), f1 = unpack2(p1);
        float sa = (f0.x + f0.y) + (f1.x + f1.y);
        sa += __shfl_xor_sync(0xffffffffu, sa, 1);
        sa += __shfl_xor_sync(0xffffffffu, sa, 2);
        const u64 sa2 = pack2(sa, sa);
        const float vi = s_v[i];
        const u64 vi2 = pack2(vi, vi);

        u64 o0 = 0ULL, o1 = 0ULL;
#pragma unroll
        for (int g = 0; g < 4; g++) {
            ulonglong2 w2 = *(const ulonglong2*)&s_w [jb + 4*g];
            ulonglong2 b2 = *(const ulonglong2*)&s_bb[jb + 4*g];
            ulonglong2 k2 = *(const ulonglong2*)&s_k [jb + 4*g];
            ulonglong2 r2 = *(const ulonglong2*)&s_r [jb + 4*g];
            S2[2*g]   = ffma2(S2[2*g],   w2.x, ffma2(sa2, b2.x, fmul2(vi2, k2.x)));
            o0        = ffma2(S2[2*g],   r2.x, o0);
            S2[2*g+1] = ffma2(S2[2*g+1], w2.y, ffma2(sa2, b2.y, fmul2(vi2, k2.y)));
            o1        = ffma2(S2[2*g+1], r2.y, o1);
        }
        float2 q0 = unpack2(o0), q1 = unpack2(o1);
        float out = (q0.x + q0.y) + (q1.x + q1.y);
        out += __shfl_xor_sync(0xffffffffu, out, 1);
        out += __shfl_xor_sync(0xffffffffu, out, 2);
        if (jq == 0) obase[(size_t)t * Cz + i] = out;
        __syncthreads();
    }
}

// ---------------- groupnorm + rk bonus + gate -> fp16 ----------------
__global__ void post_kernel(const float* __restrict__ rk,
                            const float* __restrict__ gamma, const float* __restrict__ beta)
{
    int gw   = (blockIdx.x * blockDim.x + threadIdx.x) >> 5;
    int lane = threadIdx.x & 31;
    if (gw >= BTz * Hz) return;
    int bt = gw / Hz, h = gw % Hz;
    int c0 = h * 64 + lane, c1 = c0 + 32;
    size_t base = (size_t)bt * Cz;
    float o0 = g_o[base + c0], o1 = g_o[base + c1];
    float s1 = o0 + o1;
    float s2 = o0*o0 + o1*o1;
    float r0 = g_r[base + c0], r1 = g_r[base + c1];
    float k0 = g_k[base + c0], k1 = g_k[base + c1];
    float bon = r0 * k0 * rk[h * 64 + lane] + r1 * k1 * rk[h * 64 + lane + 32];
#pragma unroll
    for (int m = 16; m > 0; m >>= 1) {
        s1  += __shfl_xor_sync(0xffffffffu, s1,  m);
        s2  += __shfl_xor_sync(0xffffffffu, s2,  m);
        bon += __shfl_xor_sync(0xffffffffu, bon, m);
    }
    float mu   = s1 * (1.f / 64.f);
    float var  = s2 * (1.f / 64.f) - mu * mu;
    float rstd = rsqrtf(var + 0.00064f);
    float v0 = g_v[base + c0], v1 = g_v[base + c1];
    float y0 = ((o0 - mu) * rstd * gamma[c0] + beta[c0] + bon * v0) * g_g[base + c0];
    float y1 = ((o1 - mu) * rstd * gamma[c1] + beta[c1] + bon * v1) * g_g[base + c1];
    g_yg[base + c0] = __float2half_rn(y0);
    g_yg[base + c1] = __float2half_rn(y1);
}

// ---------------- host: tensormap builder ----------------
typedef CUresult (*PFN_encode)(CUtensorMap*, CUtensorMapDataType, cuuint32_t, void*,
                               const cuuint64_t*, const cuuint64_t*, const cuuint32_t*,
                               const cuuint32_t*, CUtensorMapInterleave, CUtensorMapSwizzle,
                               CUtensorMapL2promotion, CUtensorMapFloatOOBfill);

static void make_map(PFN_encode enc, CUtensorMap* m, const void* base,
                     unsigned long long d0, unsigned long long d1,
                     unsigned long long stride1B, unsigned box0, unsigned box1)
{
    cuuint64_t dims[2]    = { d0, d1 };
    cuuint64_t strides[1] = { stride1B };
    cuuint32_t box[2]     = { box0, box1 };
    cuuint32_t es[2]      = { 1, 1 };
    enc(m, CU_TENSOR_MAP_DATA_TYPE_FLOAT16, 2, (void*)base, dims, strides, box, es,
        CU_TENSOR_MAP_INTERLEAVE_NONE, CU_TENSOR_MAP_SWIZZLE_128B,
        CU_TENSOR_MAP_L2_PROMOTION_L2_128B, CU_TENSOR_MAP_FLOAT_OOB_FILL_NONE);
}

#define SMEM_128 (2048 + 4*(128*128 + 2*128*128))
#define SMEM_64  (2048 + 4*(128*128 + 2*64*128))

// ---------------- launch ----------------
extern "C" void kernel_launch(void* const* d_in, const int* in_sizes, int n_in,
                              void* d_out, int out_size)
{
    const float* x    = (const float*)d_in[0];
    const float* x_r  = (const float*)d_in[1];
    const float* x_w  = (const float*)d_in[2];
    const float* x_k  = (const float*)d_in[3];
    const float* x_v  = (const float*)d_in[4];
    const float* x_a  = (const float*)d_in[5];
    const float* x_g  = (const float*)d_in[6];
    const float* w0   = (const float*)d_in[7];
    const float* w1   = (const float*)d_in[8];
    const float* w2   = (const float*)d_in[9];
    const float* a0   = (const float*)d_in[10];
    const float* a1   = (const float*)d_in[11];
    const float* a2   = (const float*)d_in[12];
    const float* g1   = (const float*)d_in[16];
    const float* g2   = (const float*)d_in[17];
    const float* k_k  = (const float*)d_in[18];
    const float* k_a  = (const float*)d_in[19];
    const float* r_k  = (const float*)d_in[20];
    const float* Wr   = (const float*)d_in[21];
    const float* Wk   = (const float*)d_in[22];
    const float* Wv   = (const float*)d_in[23];
    const float* Wo   = (const float*)d_in[24];
    const float* lg   = (const float*)d_in[25];
    const float* lb   = (const float*)d_in[26];

    void *pr, *pk, *pv, *pwd, *pa, *pg, *paa, *pbb, *po;
    void *px6, *pyg, *phid, *pwh, *pwl;
    cudaGetSymbolAddress(&pr,  g_r);   cudaGetSymbolAddress(&pk,  g_k);
    cudaGetSymbolAddress(&pv,  g_v);   cudaGetSymbolAddress(&pwd, g_wd);
    cudaGetSymbolAddress(&pa,  g_a);   cudaGetSymbolAddress(&pg,  g_g);
    cudaGetSymbolAddress(&paa, g_aa);  cudaGetSymbolAddress(&pbb, g_bb);
    cudaGetSymbolAddress(&po,  g_o);
    cudaGetSymbolAddress(&px6, g_x6);  cudaGetSymbolAddress(&pyg, g_yg);
    cudaGetSymbolAddress(&phid, g_hid);
    cudaGetSymbolAddress(&pwh, g_wh);  cudaGetSymbolAddress(&pwl, g_wl);

    float *rb = (float*)pr, *kb = (float*)pk, *vb = (float*)pv, *wd = (float*)pwd;
    float *ab = (float*)pa, *gb = (float*)pg, *aab = (float*)paa, *bbb = (float*)pbb;
    float *ob = (float*)po;
    f16 *x6 = (f16*)px6, *yg = (f16*)pyg, *hid = (f16*)phid;
    f16 *wh = (f16*)pwh, *wl = (f16*)pwl;

    const size_t S = (size_t)BTz * Cz;

    cudaFuncSetAttribute(tc_gemm<128,0>, cudaFuncAttributeMaxDynamicSharedMemorySize, SMEM_128);
    cudaFuncSetAttribute(tc_gemm<64,1>,  cudaFuncAttributeMaxDynamicSharedMemorySize, SMEM_64);

    PFN_encode enc = nullptr;
    cudaDriverEntryPointQueryResult qres;
    cudaGetDriverEntryPoint("cuTensorMapEncodeTiled", (void**)&enc,
                            cudaEnableDefault, &qres);

    // 1. transpose+split all weights into the pool
    TJobs jb;
    jb.src[0]=Wr; jb.src[1]=Wk; jb.src[2]=Wv; jb.src[3]=Wo;
    jb.src[4]=w1; jb.src[5]=a1; jb.src[6]=g1;
    jb.src[7]=w2; jb.src[8]=a2; jb.src[9]=g2;
    jb.dstoff[0]=O_Wr; jb.dstoff[1]=O_Wk; jb.dstoff[2]=O_Wv; jb.dstoff[3]=O_Wo;
    jb.dstoff[4]=O_L1; jb.dstoff[5]=O_L1+64*Cz; jb.dstoff[6]=O_L1+128*Cz;
    jb.dstoff[7]=O_W2T; jb.dstoff[8]=O_A2T; jb.dstoff[9]=O_G2T;
    jb.K[0]=jb.K[1]=jb.K[2]=jb.K[3]=Cz; jb.K[4]=jb.K[5]=jb.K[6]=Cz;
    jb.K[7]=64; jb.K[8]=64; jb.K[9]=128;
    jb.N[0]=jb.N[1]=jb.N[2]=jb.N[3]=Cz; jb.N[4]=64; jb.N[5]=64; jb.N[6]=128;
    jb.N[7]=Cz; jb.N[8]=Cz; jb.N[9]=Cz;
    int tb = 0;
    for (int j = 0; j < 10; j++) { jb.tbase[j] = tb; tb += (jb.K[j]/32)*(jb.N[j]/32); }
    jb.tbase[10] = tb;
    tsplit_kernel<<<tb, dim3(32,8)>>>(jb, wh, wl);

    // 2. token shift + mix -> fp16 streams (r=0,w=1,k=2,v=3,a=4,g=5)
    mix_kernel<<<(BTz*Cz/4 + 255)/256, 256>>>(x, x_r, x_w, x_k, x_v, x_a, x_g, x6);

    CUtensorMap mA, mBh, mBl;
    dim3 bg(Cz/128, BTz/128);

    // 3-5. LoRA stage-1 (BN=64, OUT=1 -> hidden pool fp16)
    {   // hw = tanh(xw@w1) -> hidden cols 0-63
        make_map(enc, &mA,  x6 + 1*S, Cz, BTz, Cz*2, 64, 128);
        make_map(enc, &mBh, wh + O_L1, Cz, 64, Cz*2, 64, 64);
        make_map(enc, &mBl, wl + O_L1, Cz, 64, Cz*2, 64, 64);
        tc_gemm<64,1><<<dim3(1, BTz/128), 256, SMEM_64>>>(mA, mBh, mBl, Cz,
            nullptr, hid, 256, nullptr, 1);
    }
    {   // ha = xa@a1 -> hidden cols 64-127
        make_map(enc, &mA,  x6 + 4*S, Cz, BTz, Cz*2, 64, 128);
        make_map(enc, &mBh, wh + O_L1 + 64*Cz, Cz, 64, Cz*2, 64, 64);
        make_map(enc, &mBl, wl + O_L1 + 64*Cz, Cz, 64, Cz*2, 64, 64);
        tc_gemm<64,1><<<dim3(1, BTz/128), 256, SMEM_64>>>(mA, mBh, mBl, Cz,
            nullptr, hid + 64, 256, nullptr, 0);
    }
    {   // hg = sigmoid(xg@g1) -> hidden cols 128-255
        make_map(enc, &mA,  x6 + 5*S, Cz, BTz, Cz*2, 64, 128);
        make_map(enc, &mBh, wh + O_L1 + 128*Cz, Cz, 128, Cz*2, 64, 64);
        make_map(enc, &mBl, wl + O_L1 + 128*Cz, Cz, 128, Cz*2, 64, 64);
        tc_gemm<64,1><<<dim3(2, BTz/128), 256, SMEM_64>>>(mA, mBh, mBl, Cz,
            nullptr, hid + 128, 256, nullptr, 2);
    }

    // 6-8. big projections r, k, v
    {
        make_map(enc, &mA,  x6 + 0*S, Cz, BTz, Cz*2, 64, 128);
        make_map(enc, &mBh, wh + O_Wr, Cz, Cz, Cz*2, 64, 128);
        make_map(enc, &mBl, wl + O_Wr, Cz, Cz, Cz*2, 64, 128);
        tc_gemm<128,0><<<bg, 256, SMEM_128>>>(mA, mBh, mBl, Cz,
            rb, nullptr, Cz, nullptr, 0);
    }
    {
        make_map(enc, &mA,  x6 + 2*S, Cz, BTz, Cz*2, 64, 128);
        make_map(enc, &mBh, wh + O_Wk, Cz, Cz, Cz*2, 64, 128);
        make_map(enc, &mBl, wl + O_Wk, Cz, Cz, Cz*2, 64, 128);
        tc_gemm<128,0><<<bg, 256, SMEM_128>>>(mA, mBh, mBl, Cz,
            kb, nullptr, Cz, nullptr, 0);
    }
    {
        make_map(enc, &mA,  x6 + 3*S, Cz, BTz, Cz*2, 64, 128);
        make_map(enc, &mBh, wh + O_Wv, Cz, Cz, Cz*2, 64, 128);
        make_map(enc, &mBl, wl + O_Wv, Cz, Cz, Cz*2, 64, 128);
        tc_gemm<128,0><<<bg, 256, SMEM_128>>>(mA, mBh, mBl, Cz,
            vb, nullptr, Cz, nullptr, 0);
    }

    // 9-11. LoRA stage-2
    {   // wd = decay(w0 + hw @ w2)
        make_map(enc, &mA,  hid, 64, BTz, 256*2, 64, 128);
        make_map(enc, &mBh, wh + O_W2T, 64, Cz, 64*2, 64, 128);
        make_map(enc, &mBl, wl + O_W2T, 64, Cz, 64*2, 64, 128);
        tc_gemm<128,0><<<bg, 256, SMEM_128>>>(mA, mBh, mBl, 64,
            wd, nullptr, Cz, w0, 3);
    }
    {   // a = sigmoid(a0 + ha @ a2)
        make_map(enc, &mA,  hid + 64, 64, BTz, 256*2, 64, 128);
        make_map(enc, &mBh, wh + O_A2T, 64, Cz, 64*2, 64, 128);
        make_map(enc, &mBl, wl + O_A2T, 64, Cz, 64*2, 64, 128);
        tc_gemm<128,0><<<bg, 256, SMEM_128>>>(mA, mBh, mBl, 64,
            ab, nullptr, Cz, a0, 2);
    }
    {   // g = hg @ g2
        make_map(enc, &mA,  hid + 128, 128, BTz, 256*2, 64, 128);
        make_map(enc, &mBh, wh + O_G2T, 128, Cz, 128*2, 64, 128);
        make_map(enc, &mBl, wl + O_G2T, 128, Cz, 128*2, 64, 128);
        tc_gemm<128,0><<<bg, 256, SMEM_128>>>(mA, mBh, mBl, 128,
            gb, nullptr, Cz, nullptr, 0);
    }

    // 12. kk normalize / aa / bb / k update
    prep_kernel<<<BTz*Hz/8, 256>>>(k_k, k_a);

    // 13. sequential scan
    scan_kernel<<<Bz*Hz, 256>>>(rb, wd, kb, aab, bbb, vb, ob);

    // 14. groupnorm + bonus + gate -> yg fp16
    post_kernel<<<BTz*Hz/8, 256>>>(r_k, lg, lb);

    // 15. output projection
    {
        make_map(enc, &mA,  yg, Cz, BTz, Cz*2, 64, 128);
        make_map(enc, &mBh, wh + O_Wo, Cz, Cz, Cz*2, 64, 128);
        make_map(enc, &mBl, wl + O_Wo, Cz, Cz, Cz*2, 64, 128);
        tc_gemm<128,0><<<bg, 256, SMEM_128>>>(mA, mBh, mBl, Cz,
            (float*)d_out, nullptr, Cz, nullptr, 0);
    }

    // 16. v_first if expected
    if (out_size >= 2 * BTz * Cz) {
        cudaMemcpyAsync((float*)d_out + S, vb, sizeof(float) * S, cudaMemcpyDeviceToDevice);
    }
}

// round 10
// speedup vs baseline: 2.2043x; 1.3099x over previous
#include <cuda_runtime.h>
#include <cuda.h>
#include <cuda_bf16.h>
#include <cuda_fp16.h>
#include <cstdint>
#include <math.h>

#define Bz   4
#define Tz   1024
#define Cz   1024
#define Hz   16
#define BTz  (Bz*Tz)

typedef __half  f16;
typedef __half2 f162;
typedef unsigned long long u64;

// ---------------- scratch (device globals; no allocation allowed) ----------------
__device__ float g_r [BTz*Cz], g_k [BTz*Cz], g_v [BTz*Cz], g_wd[BTz*Cz];
__device__ float g_a [BTz*Cz], g_g [BTz*Cz], g_aa[BTz*Cz], g_bb[BTz*Cz], g_o [BTz*Cz];

__device__ __align__(256) f16 g_x6[6*BTz*Cz];     // mixed streams, fp16
__device__ __align__(256) f16 g_yg[BTz*Cz];       // (gn(o)+bonus)*g fp16
// LoRA hidden pool [BTz, 256]: cols 0-63 decay, 64-127 a, 128-255 g (fp16)
__device__ __align__(256) f16 g_hid[BTz*256];

// weight pool: all matrices stored TRANSPOSED [N, K] row-major, fp16 hi/lo
#define O_Wr 0
#define O_Wk (Cz*Cz)
#define O_Wv (2*Cz*Cz)
#define O_Wo (3*Cz*Cz)
#define O_L1 (4*Cz*Cz)                  // [256, 1024]: w1t 0-63, a1t 64-127, g1t 128-255
#define O_W2T (O_L1 + 256*Cz)           // [1024, 64]
#define O_A2T (O_W2T + Cz*64)           // [1024, 64]
#define O_G2T (O_A2T + Cz*64)           // [1024, 128]
#define WPOOL (O_G2T + Cz*128)
__device__ __align__(256) f16 g_wh[WPOOL], g_wl[WPOOL];

// ---------------- helpers ----------------
__device__ __forceinline__ uint32_t su32(const void* p) {
    return (uint32_t)__cvta_generic_to_shared(p);
}
__device__ __forceinline__ void ldsm4(uint32_t& a0, uint32_t& a1, uint32_t& a2, uint32_t& a3, uint32_t addr) {
    asm volatile("ldmatrix.sync.aligned.m8n8.x4.shared.b16 {%0,%1,%2,%3},[%4];"
                 : "=r"(a0), "=r"(a1), "=r"(a2), "=r"(a3) : "r"(addr));
}
__device__ __forceinline__ void mma16816(float* c, const uint32_t* a, const uint32_t* b) {
    asm volatile("mma.sync.aligned.m16n8k16.row.col.f32.f16.f16.f32 "
                 "{%0,%1,%2,%3},{%4,%5,%6,%7},{%8,%9},{%0,%1,%2,%3};"
                 : "+f"(c[0]), "+f"(c[1]), "+f"(c[2]), "+f"(c[3])
                 : "r"(a[0]), "r"(a[1]), "r"(a[2]), "r"(a[3]), "r"(b[0]), "r"(b[1]));
}
__device__ __forceinline__ u64 ffma2(u64 a, u64 b, u64 c) {
    u64 d; asm("fma.rn.f32x2 %0,%1,%2,%3;" : "=l"(d) : "l"(a), "l"(b), "l"(c)); return d;
}
__device__ __forceinline__ u64 fmul2(u64 a, u64 b) {
    u64 d; asm("mul.rn.f32x2 %0,%1,%2;" : "=l"(d) : "l"(a), "l"(b)); return d;
}
__device__ __forceinline__ u64 pack2(float x, float y) {
    u64 d; asm("mov.b64 %0,{%1,%2};" : "=l"(d) : "f"(x), "f"(y)); return d;
}
__device__ __forceinline__ float2 unpack2(u64 a) {
    float x, y; asm("mov.b64 {%0,%1},%2;" : "=f"(x), "=f"(y) : "l"(a)); return make_float2(x, y);
}
__device__ __forceinline__ void cpa4(uint32_t dst, const void* src) {
    asm volatile("cp.async.ca.shared.global [%0], [%1], 4;" :: "r"(dst), "l"(src));
}
__device__ __forceinline__ void cpa_commit() { asm volatile("cp.async.commit_group;"); }
template<int NN> __device__ __forceinline__ void cpa_wait() { asm volatile("cp.async.wait_group %0;" :: "n"(NN)); }

// ---- mbarrier / TMA ----
#define MBARRIER_INIT(addr, cnt) \
    asm volatile("mbarrier.init.shared.b64 [%0], %1;" :: "r"((uint32_t)(addr)), "r"((uint32_t)(cnt)) : "memory")
#define MBARRIER_EXPECT_TX(addr, bytes) \
    asm volatile("mbarrier.arrive.expect_tx.shared.b64 _, [%0], %1;" :: "r"((uint32_t)(addr)), "r"((uint32_t)(bytes)) : "memory")
#define TMA2D(dst, map, cx, cy, mbar) \
    asm volatile("cp.async.bulk.tensor.2d.shared::cta.global.tile.mbarrier::complete_tx::bytes [%0],[%1,{%2,%3}],[%4];" \
        :: "r"((uint32_t)(dst)), "l"(map), "r"((int)(cx)), "r"((int)(cy)), "r"((uint32_t)(mbar)) : "memory")

__device__ __forceinline__ void mbar_wait(uint32_t addr, int phase) {
    asm volatile(
        "{\n\t.reg .pred P1;\n\t"
        "WAIT_LOOP_%=:\n\t"
        "mbarrier.try_wait.parity.shared.b64 P1, [%0], %1, 0x989680;\n\t"
        "@P1 bra.uni WAIT_DONE_%=;\n\t"
        "bra.uni WAIT_LOOP_%=;\n\t"
        "WAIT_DONE_%=:\n\t}"
        :: "r"(addr), "r"((uint32_t)phase) : "memory");
}

// ---------------- transpose + split: W[K,N] fp32 -> pool[N,K] fp16 hi/lo ----------------
struct TJobs { const float* src[10]; int dstoff[10]; int K[10]; int N[10]; int tbase[11]; };

__global__ void tsplit_kernel(TJobs jb, f16* __restrict__ hi, f16* __restrict__ lo)
{
    __shared__ float s[32][33];
    int bid = blockIdx.x;
    int j = 0;
#pragma unroll
    for (int q = 1; q < 10; q++) if (bid >= jb.tbase[q]) j = q;
    int tl = bid - jb.tbase[j];
    int K = jb.K[j], N = jb.N[j];
    int ntn = N >> 5;
    int tn = tl % ntn, tk = tl / ntn;
    const float* src = jb.src[j];
    int tx = threadIdx.x, ty = threadIdx.y;   // 32 x 8
#pragma unroll
    for (int i = 0; i < 4; i++) {
        int r = tk*32 + ty + i*8, c = tn*32 + tx;
        s[ty + i*8][tx] = src[(size_t)r * N + c];
    }
    __syncthreads();
#pragma unroll
    for (int i = 0; i < 4; i++) {
        int n = tn*32 + ty + i*8, k = tk*32 + tx;
        float v = s[tx][ty + i*8];
        f16 h = __float2half_rn(v);
        size_t di = (size_t)jb.dstoff[j] + (size_t)n * K + k;
        hi[di] = h;
        lo[di] = __float2half_rn(v - __half2float(h));
    }
}

// ---------------- token shift + 6-way mix, emitting fp16 ----------------
__global__ void mix_kernel(const float* __restrict__ x,
                           const float* __restrict__ mr, const float* __restrict__ mw,
                           const float* __restrict__ mk, const float* __restrict__ mv,
                           const float* __restrict__ ma, const float* __restrict__ mg,
                           f16* __restrict__ xo)
{
    int idx = blockIdx.x * blockDim.x + threadIdx.x;     // float4 index
    const int total = BTz * Cz / 4;
    if (idx >= total) return;
    int c4 = idx % (Cz / 4);
    int bt = idx / (Cz / 4);
    int t  = bt % Tz;
    const float4* x4 = (const float4*)x;
    float4 cur = x4[idx];
    float4 prev = make_float4(0.f, 0.f, 0.f, 0.f);
    if (t > 0) prev = x4[idx - Cz / 4];
    float4 xx = make_float4(prev.x - cur.x, prev.y - cur.y, prev.z - cur.z, prev.w - cur.w);
    int c = c4 * 4;
    const float* ms[6] = { mr, mw, mk, mv, ma, mg };
#pragma unroll
    for (int s = 0; s < 6; s++) {
        float4 mm = *(const float4*)(ms[s] + c);
        f162 h0 = __floats2half2_rn(cur.x + xx.x * mm.x, cur.y + xx.y * mm.y);
        f162 h1 = __floats2half2_rn(cur.z + xx.z * mm.z, cur.w + xx.w * mm.w);
        uint2 h; h.x = *(uint32_t*)&h0; h.y = *(uint32_t*)&h1;
        ((uint2*)(xo + (size_t)s * BTz * Cz))[idx] = h;
    }
}

// ---------------- epilogue ----------------
__device__ __forceinline__ float apply_epi_rt(float acc, float b, int epi)
{
    float pre = acc + b;
    if (epi == 0) return pre;
    if (epi == 1) return tanhf(pre);
    if (epi == 2) return 1.f / (1.f + expf(-pre));
    float sp = (pre > -30.f) ? log1pf(expf(-pre)) : -pre;   // softplus(-pre)
    return expf(-expf(-sp - 0.5f));
}

// ---------------- fused 3-job TMA + mma.sync GEMM: C = A*Bh + A*Bl ----------------
// blockIdx.z selects job (tensormaps, K, output, bias, epi). BM=128, BK=64, 2-stage.
template<int BN, int OUT>
__global__ __launch_bounds__(256, 2)
void tc_gemm3(const __grid_constant__ CUtensorMap mA0,
              const __grid_constant__ CUtensorMap mA1,
              const __grid_constant__ CUtensorMap mA2,
              const __grid_constant__ CUtensorMap mB0h,
              const __grid_constant__ CUtensorMap mB1h,
              const __grid_constant__ CUtensorMap mB2h,
              const __grid_constant__ CUtensorMap mB0l,
              const __grid_constant__ CUtensorMap mB1l,
              const __grid_constant__ CUtensorMap mB2l,
              int K0, int K1, int K2,
              float* C0, float* C1, float* C2,
              f16* H0, f16* H1, f16* H2,
              int ldc,
              const float* bias0, const float* bias1, const float* bias2,
              int epi0, int epi1, int epi2,
              int xc0, int xc1, int xc2)
{
    constexpr int BM = 128;
    constexpr int ATILE = BM*128;
    constexpr int BTILE = BN*128;
    constexpr int STAGE = ATILE + 2*BTILE;
    constexpr int NSTG = 2;
    constexpr int WM = (BN == 128) ? 64 : 32;
    constexpr int WN = 32;
    constexpr int MFR = WM/16, NFR = WN/8;

    const int z = blockIdx.z;
    const int xcnt = (z == 0) ? xc0 : (z == 1) ? xc1 : xc2;
    if ((int)blockIdx.x >= xcnt) return;

    const CUtensorMap* pA  = (z == 0) ? &mA0  : (z == 1) ? &mA1  : &mA2;
    const CUtensorMap* pBh = (z == 0) ? &mB0h : (z == 1) ? &mB1h : &mB2h;
    const CUtensorMap* pBl = (z == 0) ? &mB0l : (z == 1) ? &mB1l : &mB2l;
    const int K   = (z == 0) ? K0 : (z == 1) ? K1 : K2;
    float* C      = (z == 0) ? C0 : (z == 1) ? C1 : C2;
    f16* Ch       = (z == 0) ? H0 : (z == 1) ? H1 : H2;
    const float* bias = (z == 0) ? bias0 : (z == 1) ? bias1 : bias2;
    const int epi = (z == 0) ? epi0 : (z == 1) ? epi1 : epi2;

    extern __shared__ __align__(1024) char dsm[];
    uint32_t raw  = su32(dsm);
    uint32_t ctrl = (raw + 1023u) & ~1023u;
    uint32_t tiles = ctrl + 1024;

    const int tid = threadIdx.x, lane = tid & 31, warp = tid >> 5;
    const int wN = warp % (BN/WN), wM = warp / (BN/WN);
    const int row0 = blockIdx.y * BM, col0 = blockIdx.x * BN;
    const int T = K >> 6;

    if (tid == 0) {
#pragma unroll
        for (int s = 0; s < NSTG; s++) MBARRIER_INIT(ctrl + 16 + 8*s, 1);
    }
    __syncthreads();

    float acc[MFR][NFR][4];
#pragma unroll
    for (int i = 0; i < MFR; i++)
#pragma unroll
        for (int j = 0; j < NFR; j++)
#pragma unroll
            for (int q = 0; q < 4; q++) acc[i][j][q] = 0.f;

    const uint32_t swm = (uint32_t)((lane & 7) << 4);
    uint32_t aRow[MFR], bRow[NFR/2];
#pragma unroll
    for (int fm = 0; fm < MFR; fm++)
        aRow[fm] = (uint32_t)((wM*WM + fm*16 + (lane & 15)) * 128);
#pragma unroll
    for (int p = 0; p < NFR/2; p++)
        bRow[p] = (uint32_t)((wN*WN + p*16 + (lane & 7) + ((lane >> 4) << 3)) * 128);
    const uint32_t aColB = (uint32_t)((lane >> 4) * 16);
    const uint32_t bColB = (uint32_t)(((lane >> 3) & 1) * 16);

    auto issue_stage = [&](int s, int k0) {
        uint32_t sb = tiles + s*STAGE;
        uint32_t fb = ctrl + 16 + 8*s;
        MBARRIER_EXPECT_TX(fb, (uint32_t)STAGE);
        TMA2D(sb,             pA,  k0, row0, fb);
        TMA2D(sb+ATILE,       pBh, k0, col0, fb);
        TMA2D(sb+ATILE+BTILE, pBl, k0, col0, fb);
    };

    if (tid == 0) {
        const int npre = (T < NSTG) ? T : NSTG;
        for (int s = 0; s < npre; s++) issue_stage(s, s*64);
    }

    int ph[NSTG];
#pragma unroll
    for (int s = 0; s < NSTG; s++) ph[s] = 0;

    for (int t = 0; t < T; t++) {
        const int s = t & (NSTG-1);
        mbar_wait(ctrl + 16 + 8*s, ph[s]);
        ph[s] ^= 1;
        const uint32_t aB = tiles + s*STAGE;
        const uint32_t bH = aB + ATILE;
        const uint32_t bL = bH + BTILE;
#pragma unroll
        for (int kk = 0; kk < 4; kk++) {
            const uint32_t aC = (uint32_t)(kk*32) + aColB;
            const uint32_t bC = (uint32_t)(kk*32) + bColB;
            uint32_t Af[MFR][4], Bfh[NFR][2], Bfl[NFR][2];
#pragma unroll
            for (int fm = 0; fm < MFR; fm++) {
                uint32_t off = aRow[fm] + (aC ^ swm);
                ldsm4(Af[fm][0], Af[fm][1], Af[fm][2], Af[fm][3], aB + off);
            }
#pragma unroll
            for (int p = 0; p < NFR/2; p++) {
                uint32_t off = bRow[p] + (bC ^ swm);
                uint32_t t0, t1, t2, t3;
                ldsm4(t0, t1, t2, t3, bH + off);
                Bfh[2*p][0] = t0; Bfh[2*p][1] = t1; Bfh[2*p+1][0] = t2; Bfh[2*p+1][1] = t3;
                ldsm4(t0, t1, t2, t3, bL + off);
                Bfl[2*p][0] = t0; Bfl[2*p][1] = t1; Bfl[2*p+1][0] = t2; Bfl[2*p+1][1] = t3;
            }
#pragma unroll
            for (int fm = 0; fm < MFR; fm++)
#pragma unroll
                for (int fn = 0; fn < NFR; fn++) {
                    mma16816(acc[fm][fn], Af[fm], Bfh[fn]);
                    mma16816(acc[fm][fn], Af[fm], Bfl[fn]);
                }
        }
        __syncthreads();
        if (tid == 0 && t + NSTG < T) issue_stage(s, (t + NSTG) * 64);
    }

    // epilogue
#pragma unroll
    for (int fm = 0; fm < MFR; fm++) {
        int r = row0 + wM*WM + fm*16 + (lane >> 2);
#pragma unroll
        for (int fn = 0; fn < NFR; fn++) {
            int c = col0 + wN*WN + fn*8 + 2*(lane & 3);
            float b0 = bias ? bias[c] : 0.f;
            float b1 = bias ? bias[c+1] : 0.f;
            float x0 = apply_epi_rt(acc[fm][fn][0], b0, epi);
            float x1 = apply_epi_rt(acc[fm][fn][1], b1, epi);
            float x2 = apply_epi_rt(acc[fm][fn][2], b0, epi);
            float x3 = apply_epi_rt(acc[fm][fn][3], b1, epi);
            if (OUT == 0) {
                *(float2*)&C[(size_t)r*ldc + c]     = make_float2(x0, x1);
                *(float2*)&C[(size_t)(r+8)*ldc + c] = make_float2(x2, x3);
            } else {
                f162 h0 = __floats2half2_rn(x0, x1);
                f162 h1 = __floats2half2_rn(x2, x3);
                *(f162*)&Ch[(size_t)r*ldc + c]     = h0;
                *(f162*)&Ch[(size_t)(r+8)*ldc + c] = h1;
            }
        }
    }
}

// ---------------- kk normalize, aa, bb, k update ----------------
__global__ void prep_kernel(const float* __restrict__ kkw, const float* __restrict__ kaw)
{
    int gw   = (blockIdx.x * blockDim.x + threadIdx.x) >> 5;
    int lane = threadIdx.x & 31;
    if (gw >= BTz * Hz) return;
    int bt = gw / Hz, h = gw % Hz;
    int c0 = h * 64 + lane, c1 = c0 + 32;
    size_t base = (size_t)bt * Cz;
    float k0 = g_k[base + c0], k1 = g_k[base + c1];
    float kk0 = k0 * kkw[c0], kk1 = k1 * kkw[c1];
    float ss = kk0*kk0 + kk1*kk1;
#pragma unroll
    for (int m = 16; m > 0; m >>= 1) ss += __shfl_xor_sync(0xffffffffu, ss, m);
    float inv = 1.f / fmaxf(sqrtf(ss), 1e-12f);
    float a0 = g_a[base + c0], a1v = g_a[base + c1];
    kk0 *= inv; kk1 *= inv;
    g_aa[base + c0] = -kk0;       g_aa[base + c1] = -kk1;
    g_bb[base + c0] = kk0 * a0;   g_bb[base + c1] = kk1 * a1v;
    g_k [base + c0] = k0 * (1.f + (a0  - 1.f) * kaw[c0]);
    g_k [base + c1] = k1 * (1.f + (a1v - 1.f) * kaw[c1]);
}

// ---------------- sequential RWKV7 scan: cp.async 3-buffer prefetch pipeline ----------------
// 256 threads: tid = i*4 + jq; thread owns S[i][jq*16 .. jq*16+15] as 8 f32x2.
__global__ __launch_bounds__(256)
void scan_kernel(const float* __restrict__ r, const float* __restrict__ wdec,
                 const float* __restrict__ k, const float* __restrict__ aa,
                 const float* __restrict__ bb, const float* __restrict__ v,
                 float* __restrict__ o)
{
    const int bh = blockIdx.x;
    const int b = bh / Hz, h = bh % Hz;
    const int tid = threadIdx.x;
    const int i  = tid >> 2;
    const int jq = tid & 3;
    const int jb = jq * 16;

    __shared__ __align__(16) float sm[3][6*64];   // r,w,k,aa,bb,v @ stride 64
    u64 S2[8];
#pragma unroll
    for (int q = 0; q < 8; q++) S2[q] = 0ULL;

    const size_t base = (size_t)b * Tz * Cz + h * 64;
    const float* vp[6] = { r + base, wdec + base, k + base, aa + base, bb + base, v + base };

    const float* myp[2]; int mys[2]; int nslot = (tid < 128) ? 2 : 1;
#pragma unroll
    for (int u = 0; u < 2; u++) {
        int lin = u * 256 + tid;
        if (lin >= 384) lin = 0;
        int vec = lin >> 6;
        int idx = lin & 63;
        const float* p = vp[0];
        if (vec == 1) p = vp[1]; else if (vec == 2) p = vp[2];
        else if (vec == 3) p = vp[3]; else if (vec == 4) p = vp[4];
        else if (vec == 5) p = vp[5];
        myp[u] = p + idx;
        mys[u] = lin;
    }

    // prologue: async groups for t=0 (buf0) and t=1 (buf1)
    for (int u = 0; u < nslot; u++) cpa4(su32(&sm[0][mys[u]]), myp[u]);
    cpa_commit();
    for (int u = 0; u < nslot; u++) cpa4(su32(&sm[1][mys[u]]), myp[u] + Cz);
    cpa_commit();

    float* obase = o + base;
    int cur = 0;
    for (int t = 0; t < Tz; t++) {
        cpa_wait<1>();          // my copies for step t complete (t+1 may be pending)
        __syncthreads();        // all threads' copies for t visible; reads of buf[(t+2)%3] (from t-1) done
        // issue prefetch for t+2 into the buffer read at t-1
        int nb = cur + 2; if (nb >= 3) nb -= 3;
        if (t + 2 < Tz) {
            const size_t off = (size_t)(t + 2) * Cz;
            for (int u = 0; u < nslot; u++) cpa4(su32(&sm[nb][mys[u]]), myp[u] + off);
        }
        cpa_commit();

        const float* s_r  = &sm[cur][0];
        const float* s_w  = &sm[cur][64];
        const float* s_k  = &sm[cur][128];
        const float* s_aa = &sm[cur][192];
        const float* s_bb = &sm[cur][256];
        const float* s_v  = &sm[cur][320];

        u64 p0 = 0ULL, p1 = 0ULL;
#pragma unroll
        for (int g = 0; g < 4; g++) {
            ulonglong2 a2 = *(const ulonglong2*)&s_aa[jb + 4*g];
            p0 = ffma2(S2[2*g],   a2.x, p0);
            p1 = ffma2(S2[2*g+1], a2.y, p1);
        }
        float2 f0 = unpack2(p0), f1 = unpack2(p1);
        float sa = (f0.x + f0.y) + (f1.x + f1.y);
        sa += __shfl_xor_sync(0xffffffffu, sa, 1);
        sa += __shfl_xor_sync(0xffffffffu, sa, 2);
        const u64 sa2 = pack2(sa, sa);
        const float vi = s_v[i];
        const u64 vi2 = pack2(vi, vi);

        u64 o0 = 0ULL, o1 = 0ULL;
#pragma unroll
        for (int g = 0; g < 4; g++) {
            ulonglong2 w2 = *(const ulonglong2*)&s_w [jb + 4*g];
            ulonglong2 b2 = *(const ulonglong2*)&s_bb[jb + 4*g];
            ulonglong2 k2 = *(const ulonglong2*)&s_k [jb + 4*g];
            ulonglong2 r2 = *(const ulonglong2*)&s_r [jb + 4*g];
            S2[2*g]   = ffma2(S2[2*g],   w2.x, ffma2(sa2, b2.x, fmul2(vi2, k2.x)));
            o0        = ffma2(S2[2*g],   r2.x, o0);
            S2[2*g+1] = ffma2(S2[2*g+1], w2.y, ffma2(sa2, b2.y, fmul2(vi2, k2.y)));
            o1        = ffma2(S2[2*g+1], r2.y, o1);
        }
        float2 q0 = unpack2(o0), q1 = unpack2(o1);
        float out = (q0.x + q0.y) + (q1.x + q1.y);
        out += __shfl_xor_sync(0xffffffffu, out, 1);
        out += __shfl_xor_sync(0xffffffffu, out, 2);
        if (jq == 0) obase[(size_t)t * Cz + i] = out;

        cur++; if (cur >= 3) cur = 0;
    }
}

// ---------------- groupnorm + rk bonus + gate -> fp16 ----------------
__global__ void post_kernel(const float* __restrict__ rk,
                            const float* __restrict__ gamma, const float* __restrict__ beta)
{
    int gw   = (blockIdx.x * blockDim.x + threadIdx.x) >> 5;
    int lane = threadIdx.x & 31;
    if (gw >= BTz * Hz) return;
    int bt = gw / Hz, h = gw % Hz;
    int c0 = h * 64 + lane, c1 = c0 + 32;
    size_t base = (size_t)bt * Cz;
    float o0 = g_o[base + c0], o1 = g_o[base + c1];
    float s1 = o0 + o1;
    float s2 = o0*o0 + o1*o1;
    float r0 = g_r[base + c0], r1 = g_r[base + c1];
    float k0 = g_k[base + c0], k1 = g_k[base + c1];
    float bon = r0 * k0 * rk[h * 64 + lane] + r1 * k1 * rk[h * 64 + lane + 32];
#pragma unroll
    for (int m = 16; m > 0; m >>= 1) {
        s1  += __shfl_xor_sync(0xffffffffu, s1,  m);
        s2  += __shfl_xor_sync(0xffffffffu, s2,  m);
        bon += __shfl_xor_sync(0xffffffffu, bon, m);
    }
    float mu   = s1 * (1.f / 64.f);
    float var  = s2 * (1.f / 64.f) - mu * mu;
    float rstd = rsqrtf(var + 0.00064f);
    float v0 = g_v[base + c0], v1 = g_v[base + c1];
    float y0 = ((o0 - mu) * rstd * gamma[c0] + beta[c0] + bon * v0) * g_g[base + c0];
    float y1 = ((o1 - mu) * rstd * gamma[c1] + beta[c1] + bon * v1) * g_g[base + c1];
    g_yg[base + c0] = __float2half_rn(y0);
    g_yg[base + c1] = __float2half_rn(y1);
}

// ---------------- host: tensormap builder ----------------
typedef CUresult (*PFN_encode)(CUtensorMap*, CUtensorMapDataType, cuuint32_t, void*,
                               const cuuint64_t*, const cuuint64_t*, const cuuint32_t*,
                               const cuuint32_t*, CUtensorMapInterleave, CUtensorMapSwizzle,
                               CUtensorMapL2promotion, CUtensorMapFloatOOBfill);

static void make_map(PFN_encode enc, CUtensorMap* m, const void* base,
                     unsigned long long d0, unsigned long long d1,
                     unsigned long long stride1B, unsigned box0, unsigned box1)
{
    cuuint64_t dims[2]    = { d0, d1 };
    cuuint64_t strides[1] = { stride1B };
    cuuint32_t box[2]     = { box0, box1 };
    cuuint32_t es[2]      = { 1, 1 };
    enc(m, CU_TENSOR_MAP_DATA_TYPE_FLOAT16, 2, (void*)base, dims, strides, box, es,
        CU_TENSOR_MAP_INTERLEAVE_NONE, CU_TENSOR_MAP_SWIZZLE_128B,
        CU_TENSOR_MAP_L2_PROMOTION_L2_128B, CU_TENSOR_MAP_FLOAT_OOB_FILL_NONE);
}

#define SMEM_128 (2048 + 2*(128*128 + 2*128*128))
#define SMEM_64  (2048 + 2*(128*128 + 2*64*128))

// ---------------- launch ----------------
extern "C" void kernel_launch(void* const* d_in, const int* in_sizes, int n_in,
                              void* d_out, int out_size)
{
    const float* x    = (const float*)d_in[0];
    const float* x_r  = (const float*)d_in[1];
    const float* x_w  = (const float*)d_in[2];
    const float* x_k  = (const float*)d_in[3];
    const float* x_v  = (const float*)d_in[4];
    const float* x_a  = (const float*)d_in[5];
    const float* x_g  = (const float*)d_in[6];
    const float* w0   = (const float*)d_in[7];
    const float* w1   = (const float*)d_in[8];
    const float* w2   = (const float*)d_in[9];
    const float* a0   = (const float*)d_in[10];
    const float* a1   = (const float*)d_in[11];
    const float* a2   = (const float*)d_in[12];
    const float* g1   = (const float*)d_in[16];
    const float* g2   = (const float*)d_in[17];
    const float* k_k  = (const float*)d_in[18];
    const float* k_a  = (const float*)d_in[19];
    const float* r_k  = (const float*)d_in[20];
    const float* Wr   = (const float*)d_in[21];
    const float* Wk   = (const float*)d_in[22];
    const float* Wv   = (const float*)d_in[23];
    const float* Wo   = (const float*)d_in[24];
    const float* lg   = (const float*)d_in[25];
    const float* lb   = (const float*)d_in[26];

    void *pr, *pk, *pv, *pwd, *pa, *pg, *paa, *pbb, *po;
    void *px6, *pyg, *phid, *pwh, *pwl;
    cudaGetSymbolAddress(&pr,  g_r);   cudaGetSymbolAddress(&pk,  g_k);
    cudaGetSymbolAddress(&pv,  g_v);   cudaGetSymbolAddress(&pwd, g_wd);
    cudaGetSymbolAddress(&pa,  g_a);   cudaGetSymbolAddress(&pg,  g_g);
    cudaGetSymbolAddress(&paa, g_aa);  cudaGetSymbolAddress(&pbb, g_bb);
    cudaGetSymbolAddress(&po,  g_o);
    cudaGetSymbolAddress(&px6, g_x6);  cudaGetSymbolAddress(&pyg, g_yg);
    cudaGetSymbolAddress(&phid, g_hid);
    cudaGetSymbolAddress(&pwh, g_wh);  cudaGetSymbolAddress(&pwl, g_wl);

    float *rb = (float*)pr, *kb = (float*)pk, *vb = (float*)pv, *wd = (float*)pwd;
    float *ab = (float*)pa, *gb = (float*)pg, *aab = (float*)paa, *bbb = (float*)pbb;
    float *ob = (float*)po;
    f16 *x6 = (f16*)px6, *yg = (f16*)pyg, *hid = (f16*)phid;
    f16 *wh = (f16*)pwh, *wl = (f16*)pwl;

    const size_t S = (size_t)BTz * Cz;

    cudaFuncSetAttribute(tc_gemm3<128,0>, cudaFuncAttributeMaxDynamicSharedMemorySize, SMEM_128);
    cudaFuncSetAttribute(tc_gemm3<64,1>,  cudaFuncAttributeMaxDynamicSharedMemorySize, SMEM_64);

    PFN_encode enc = nullptr;
    cudaDriverEntryPointQueryResult qres;
    cudaGetDriverEntryPoint("cuTensorMapEncodeTiled", (void**)&enc,
                            cudaEnableDefault, &qres);

    // 1. transpose+split all weights into the pool
    TJobs jb;
    jb.src[0]=Wr; jb.src[1]=Wk; jb.src[2]=Wv; jb.src[3]=Wo;
    jb.src[4]=w1; jb.src[5]=a1; jb.src[6]=g1;
    jb.src[7]=w2; jb.src[8]=a2; jb.src[9]=g2;
    jb.dstoff[0]=O_Wr; jb.dstoff[1]=O_Wk; jb.dstoff[2]=O_Wv; jb.dstoff[3]=O_Wo;
    jb.dstoff[4]=O_L1; jb.dstoff[5]=O_L1+64*Cz; jb.dstoff[6]=O_L1+128*Cz;
    jb.dstoff[7]=O_W2T; jb.dstoff[8]=O_A2T; jb.dstoff[9]=O_G2T;
    jb.K[0]=jb.K[1]=jb.K[2]=jb.K[3]=Cz; jb.K[4]=jb.K[5]=jb.K[6]=Cz;
    jb.K[7]=64; jb.K[8]=64; jb.K[9]=128;
    jb.N[0]=jb.N[1]=jb.N[2]=jb.N[3]=Cz; jb.N[4]=64; jb.N[5]=64; jb.N[6]=128;
    jb.N[7]=Cz; jb.N[8]=Cz; jb.N[9]=Cz;
    int tb = 0;
    for (int j = 0; j < 10; j++) { jb.tbase[j] = tb; tb += (jb.K[j]/32)*(jb.N[j]/32); }
    jb.tbase[10] = tb;
    tsplit_kernel<<<tb, dim3(32,8)>>>(jb, wh, wl);

    // 2. token shift + mix -> fp16 streams (r=0,w=1,k=2,v=3,a=4,g=5)
    mix_kernel<<<(BTz*Cz/4 + 255)/256, 256>>>(x, x_r, x_w, x_k, x_v, x_a, x_g, x6);

    CUtensorMap A0, A1, A2, B0h, B1h, B2h, B0l, B1l, B2l;

    // 3. fused LoRA stage-1: z0 hw=tanh(xw@w1), z1 ha=xa@a1, z2 hg=sig(xg@g1)
    make_map(enc, &A0,  x6 + 1*S, Cz, BTz, Cz*2, 64, 128);
    make_map(enc, &A1,  x6 + 4*S, Cz, BTz, Cz*2, 64, 128);
    make_map(enc, &A2,  x6 + 5*S, Cz, BTz, Cz*2, 64, 128);
    make_map(enc, &B0h, wh + O_L1,          Cz, 64,  Cz*2, 64, 64);
    make_map(enc, &B1h, wh + O_L1 + 64*Cz,  Cz, 64,  Cz*2, 64, 64);
    make_map(enc, &B2h, wh + O_L1 + 128*Cz, Cz, 128, Cz*2, 64, 64);
    make_map(enc, &B0l, wl + O_L1,          Cz, 64,  Cz*2, 64, 64);
    make_map(enc, &B1l, wl + O_L1 + 64*Cz,  Cz, 64,  Cz*2, 64, 64);
    make_map(enc, &B2l, wl + O_L1 + 128*Cz, Cz, 128, Cz*2, 64, 64);
    tc_gemm3<64,1><<<dim3(2, BTz/128, 3), 256, SMEM_64>>>(
        A0, A1, A2, B0h, B1h, B2h, B0l, B1l, B2l,
        Cz, Cz, Cz,
        nullptr, nullptr, nullptr,
        hid, hid + 64, hid + 128,
        256, nullptr, nullptr, nullptr,
        1, 0, 2, 1, 1, 2);

    // 4. fused big projections: z0 r, z1 k, z2 v
    make_map(enc, &A0,  x6 + 0*S, Cz, BTz, Cz*2, 64, 128);
    make_map(enc, &A1,  x6 + 2*S, Cz, BTz, Cz*2, 64, 128);
    make_map(enc, &A2,  x6 + 3*S, Cz, BTz, Cz*2, 64, 128);
    make_map(enc, &B0h, wh + O_Wr, Cz, Cz, Cz*2, 64, 128);
    make_map(enc, &B1h, wh + O_Wk, Cz, Cz, Cz*2, 64, 128);
    make_map(enc, &B2h, wh + O_Wv, Cz, Cz, Cz*2, 64, 128);
    make_map(enc, &B0l, wl + O_Wr, Cz, Cz, Cz*2, 64, 128);
    make_map(enc, &B1l, wl + O_Wk, Cz, Cz, Cz*2, 64, 128);
    make_map(enc, &B2l, wl + O_Wv, Cz, Cz, Cz*2, 64, 128);
    tc_gemm3<128,0><<<dim3(8, BTz/128, 3), 256, SMEM_128>>>(
        A0, A1, A2, B0h, B1h, B2h, B0l, B1l, B2l,
        Cz, Cz, Cz,
        rb, kb, vb,
        nullptr, nullptr, nullptr,
        Cz, nullptr, nullptr, nullptr,
        0, 0, 0, 8, 8, 8);

    // 5. fused LoRA stage-2: z0 wd=decay(w0+hw@w2), z1 a=sig(a0+ha@a2), z2 g=hg@g2
    make_map(enc, &A0,  hid,       64,  BTz, 256*2, 64, 128);
    make_map(enc, &A1,  hid + 64,  64,  BTz, 256*2, 64, 128);
    make_map(enc, &A2,  hid + 128, 128, BTz, 256*2, 64, 128);
    make_map(enc, &B0h, wh + O_W2T, 64,  Cz, 64*2,  64, 128);
    make_map(enc, &B1h, wh + O_A2T, 64,  Cz, 64*2,  64, 128);
    make_map(enc, &B2h, wh + O_G2T, 128, Cz, 128*2, 64, 128);
    make_map(enc, &B0l, wl + O_W2T, 64,  Cz, 64*2,  64, 128);
    make_map(enc, &B1l, wl + O_A2T, 64,  Cz, 64*2,  64, 128);
    make_map(enc, &B2l, wl + O_G2T, 128, Cz, 128*2, 64, 128);
    tc_gemm3<128,0><<<dim3(8, BTz/128, 3), 256, SMEM_128>>>(
        A0, A1, A2, B0h, B1h, B2h, B0l, B1l, B2l,
        64, 64, 128,
        wd, ab, gb,
        nullptr, nullptr, nullptr,
        Cz, w0, a0, nullptr,
        3, 2, 0, 8, 8, 8);

    // 6. kk normalize / aa / bb / k update
    prep_kernel<<<BTz*Hz/8, 256>>>(k_k, k_a);

    // 7. sequential scan (cp.async prefetch pipeline)
    scan_kernel<<<Bz*Hz, 256>>>(rb, wd, kb, aab, bbb, vb, ob);

    // 8. groupnorm + bonus + gate -> yg fp16
    post_kernel<<<BTz*Hz/8, 256>>>(r_k, lg, lb);

    // 9. output projection (single job via z-dim 1)
    make_map(enc, &A0,  yg, Cz, BTz, Cz*2, 64, 128);
    make_map(enc, &B0h, wh + O_Wo, Cz, Cz, Cz*2, 64, 128);
    make_map(enc, &B0l, wl + O_Wo, Cz, Cz, Cz*2, 64, 128);
    tc_gemm3<128,0><<<dim3(8, BTz/128, 1), 256, SMEM_128>>>(
        A0, A0, A0, B0h, B0h, B0h, B0l, B0l, B0l,
        Cz, Cz, Cz,
        (float*)d_out, nullptr, nullptr,
        nullptr, nullptr, nullptr,
        Cz, nullptr, nullptr, nullptr,
        0, 0, 0, 8, 0, 0);

    // 10. v_first if expected
    if (out_size >= 2 * BTz * Cz) {
        cudaMemcpyAsync((float*)d_out + S, vb, sizeof(float) * S, cudaMemcpyDeviceToDevice);
    }
}